// round 1
// baseline (speedup 1.0000x reference)
#include <cuda_runtime.h>

#define NN 16384
#define DD 128
#define KG 64
#define BM 64
#define BN 64
#define SKS 65   // padded smem row stride for 64-wide tiles (2-way max conflicts)

// ---------------- scratch (no allocs allowed -> __device__ globals) ----------------
__device__ float g_g [NN*KG];   // graph-learning projection (relu)      [N,64]
__device__ float g_h [NN*DD];   // gnn projection                         [N,128]
__device__ float g_sq[NN];      // row squared norms of g                 [N]
__device__ float g_x1[NN*DD];   // layer-0 output                         [N,128]
__device__ float g_x2[NN*DD];   // layer-1 output                         [N,128]

// ---------------- small GEMM: out[N,CO] = act(x[N,128] @ W[128,CO] + b) ----------------
template<int CO, bool RELU>
__global__ __launch_bounds__(256)
void proj_kernel(const float* __restrict__ x, const float* __restrict__ W,
                 const float* __restrict__ b, float* __restrict__ out)
{
    __shared__ float sX[64 * DD];
    const int tid  = threadIdx.x;
    const long row0 = (long)blockIdx.x * 64;

    #pragma unroll 4
    for (int i = tid; i < 64 * DD; i += 256)
        sX[i] = x[row0 * DD + i];
    __syncthreads();

    constexpr int RPT = CO / 4;       // rows per thread (CO=128 -> 32, CO=64 -> 16)
    const int c  = tid % CO;
    const int rg = tid / CO;

    float acc[RPT];
    #pragma unroll
    for (int i = 0; i < RPT; i++) acc[i] = 0.f;

    #pragma unroll 4
    for (int k = 0; k < DD; k++) {
        const float wv = W[k * CO + c];
        #pragma unroll
        for (int rr = 0; rr < RPT; rr++)
            acc[rr] = fmaf(sX[(rg * RPT + rr) * DD + k], wv, acc[rr]);
    }

    const float bv = b[c];
    #pragma unroll
    for (int rr = 0; rr < RPT; rr++) {
        float v = acc[rr] + bv;
        if (RELU) v = fmaxf(v, 0.f);
        out[(row0 + rg * RPT + rr) * CO + c] = v;
    }
}

// ---------------- row squared norms of g: sq[i] = sum_k g[i,k]^2 ----------------
__global__ __launch_bounds__(256)
void sq_kernel(const float* __restrict__ g, float* __restrict__ sq)
{
    const int warp = (blockIdx.x * blockDim.x + threadIdx.x) >> 5;
    const int lane = threadIdx.x & 31;
    if (warp >= NN) return;
    float a = g[warp * KG + lane];
    float c = g[warp * KG + 32 + lane];
    float s = a * a + c * c;
    #pragma unroll
    for (int off = 16; off; off >>= 1) s += __shfl_xor_sync(~0u, s, off);
    if (lane == 0) sq[warp] = s;
}

// ---------------- fused layer: out = (adj @ h) / rowsum(adj), adj = sigmoid(th - t*dist) --------
// dist[i,j] = sq[i] + sq[j] - 2 * g_i . g_j     (flash-attention-style, adj never materialized)
__global__ __launch_bounds__(256)
void fused_kernel(const float* __restrict__ g, const float* __restrict__ h,
                  const float* __restrict__ sq, float* __restrict__ out,
                  const float* __restrict__ tempp, const float* __restrict__ thetap,
                  int do_relu)
{
    extern __shared__ float sm[];
    float* sV  = sm;                    // [BN, 128]  (16B aligned for float4)
    float* sQ  = sV + BN * DD;          // [BM, SKS]
    float* sK  = sQ + BM * SKS;         // [BN, SKS]  (reused for W after GEMM1)
    float* sqI = sK + BN * SKS;         // [BM]
    float* sqJ = sqI + BM;              // [BN]

    const int tid  = threadIdx.x;
    const int row0 = blockIdx.x * BM;
    const float t  = 1.0f + *tempp;
    const float th = 5.0f + *thetap;
    const float t2 = 2.0f * t;
    const int ty = tid >> 4;            // 0..15 -> Q-row group (4 rows)
    const int tx = tid & 15;            // 0..15 -> col group

    // load persistent Q tile + sqI
    for (int i = tid; i < BM * KG; i += 256) {
        int r = i >> 6, c = i & 63;
        sQ[r * SKS + c] = g[(long)(row0 + r) * KG + c];
    }
    if (tid < BM) sqI[tid] = sq[row0 + tid];

    float acc[4][8];
    float rsum[4];
    #pragma unroll
    for (int i = 0; i < 4; i++) {
        rsum[i] = 0.f;
        #pragma unroll
        for (int c = 0; c < 8; c++) acc[i][c] = 0.f;
    }
    __syncthreads();

    for (int j0 = 0; j0 < NN; j0 += BN) {
        // load K/V tiles
        for (int i = tid; i < BN * KG; i += 256) {
            int r = i >> 6, c = i & 63;
            sK[r * SKS + c] = g[(long)(j0 + r) * KG + c];
        }
        #pragma unroll 4
        for (int i = tid; i < BN * DD; i += 256)
            sV[i] = h[(long)j0 * DD + i];
        if (tid < BN) sqJ[tid] = sq[j0 + tid];
        __syncthreads();

        // GEMM1: S = Q . K^T  (each thread: 4x4)
        float S[4][4];
        #pragma unroll
        for (int i = 0; i < 4; i++)
            #pragma unroll
            for (int jj = 0; jj < 4; jj++) S[i][jj] = 0.f;

        #pragma unroll 4
        for (int k = 0; k < KG; k++) {
            float qv[4], kv[4];
            #pragma unroll
            for (int i = 0; i < 4; i++)  qv[i]  = sQ[(ty * 4 + i) * SKS + k];
            #pragma unroll
            for (int jj = 0; jj < 4; jj++) kv[jj] = sK[(tx * 4 + jj) * SKS + k];
            #pragma unroll
            for (int i = 0; i < 4; i++)
                #pragma unroll
                for (int jj = 0; jj < 4; jj++)
                    S[i][jj] = fmaf(qv[i], kv[jj], S[i][jj]);
        }
        __syncthreads();   // done reading sK -> safe to overwrite with W

        // sigmoid weights -> sK (as W)
        #pragma unroll
        for (int i = 0; i < 4; i++) {
            const float base = th - t * sqI[ty * 4 + i];
            #pragma unroll
            for (int jj = 0; jj < 4; jj++) {
                float z = fmaf(t2, S[i][jj], base - t * sqJ[tx * 4 + jj]);
                float w = 1.0f / (1.0f + __expf(-z));
                sK[(ty * 4 + i) * SKS + (tx * 4 + jj)] = w;
            }
        }
        __syncthreads();

        // GEMM2: acc += W . V ; rsum += W . 1   (each thread: 4 rows x 8 cols)
        #pragma unroll 2
        for (int j = 0; j < BN; j++) {
            const float4 va = *(const float4*)(sV + j * DD + tx * 8);
            const float4 vb = *(const float4*)(sV + j * DD + tx * 8 + 4);
            #pragma unroll
            for (int i = 0; i < 4; i++) {
                const float wv = sK[(ty * 4 + i) * SKS + j];
                rsum[i] += wv;
                acc[i][0] = fmaf(wv, va.x, acc[i][0]);
                acc[i][1] = fmaf(wv, va.y, acc[i][1]);
                acc[i][2] = fmaf(wv, va.z, acc[i][2]);
                acc[i][3] = fmaf(wv, va.w, acc[i][3]);
                acc[i][4] = fmaf(wv, vb.x, acc[i][4]);
                acc[i][5] = fmaf(wv, vb.y, acc[i][5]);
                acc[i][6] = fmaf(wv, vb.z, acc[i][6]);
                acc[i][7] = fmaf(wv, vb.w, acc[i][7]);
            }
        }
        __syncthreads();   // before next tile overwrites sK/sV
    }

    // normalize (+ optional relu) and store
    #pragma unroll
    for (int i = 0; i < 4; i++) {
        const float inv = 1.0f / rsum[i];
        float o[8];
        #pragma unroll
        for (int c = 0; c < 8; c++) {
            float v = acc[i][c] * inv;
            o[c] = do_relu ? fmaxf(v, 0.f) : v;
        }
        float* dst = out + (long)(row0 + ty * 4 + i) * DD + tx * 8;
        *(float4*)(dst)     = make_float4(o[0], o[1], o[2], o[3]);
        *(float4*)(dst + 4) = make_float4(o[4], o[5], o[6], o[7]);
    }
}

// ---------------- output head: softmax(x @ out_w + out_b), one warp per row ----------------
__global__ __launch_bounds__(256)
void out_kernel(const float* __restrict__ x, const float* __restrict__ W,
                const float* __restrict__ b, float* __restrict__ out)
{
    const int row  = (blockIdx.x * blockDim.x + threadIdx.x) >> 5;
    const int lane = threadIdx.x & 31;
    if (row >= NN) return;

    const float* xr = x + (long)row * DD;
    float acc = 0.f;
    if (lane < 10) {
        #pragma unroll 8
        for (int k = 0; k < DD; k++)
            acc = fmaf(xr[k], W[k * 10 + lane], acc);
        acc += b[lane];
    }
    float m = (lane < 10) ? acc : -3.402823466e38f;
    #pragma unroll
    for (int off = 16; off; off >>= 1) m = fmaxf(m, __shfl_xor_sync(~0u, m, off));
    float e = (lane < 10) ? __expf(acc - m) : 0.f;
    float s = e;
    #pragma unroll
    for (int off = 16; off; off >>= 1) s += __shfl_xor_sync(~0u, s, off);
    if (lane < 10) out[(long)row * 10 + lane] = e / s;
}

// ---------------- launch ----------------
extern "C" void kernel_launch(void* const* d_in, const int* in_sizes, int n_in,
                              void* d_out, int out_size)
{
    const float* feat   = (const float*)d_in[0];
    const float* gl_w0  = (const float*)d_in[1];
    const float* gl_b0  = (const float*)d_in[2];
    const float* gl_w1  = (const float*)d_in[3];
    const float* gl_b1  = (const float*)d_in[4];
    const float* gnn_w0 = (const float*)d_in[5];
    const float* gnn_b0 = (const float*)d_in[6];
    const float* gnn_w1 = (const float*)d_in[7];
    const float* gnn_b1 = (const float*)d_in[8];
    const float* out_w  = (const float*)d_in[9];
    const float* out_b  = (const float*)d_in[10];
    const float* temp   = (const float*)d_in[11];
    const float* theta  = (const float*)d_in[12];
    float* out = (float*)d_out;

    float *pg, *ph, *psq, *px1, *px2;
    cudaGetSymbolAddress((void**)&pg,  g_g);
    cudaGetSymbolAddress((void**)&ph,  g_h);
    cudaGetSymbolAddress((void**)&psq, g_sq);
    cudaGetSymbolAddress((void**)&px1, g_x1);
    cudaGetSymbolAddress((void**)&px2, g_x2);

    const int fsm = (BN * DD + BM * SKS + BN * SKS + BM + BN) * (int)sizeof(float);
    cudaFuncSetAttribute(fused_kernel, cudaFuncAttributeMaxDynamicSharedMemorySize, fsm);

    // ---- layer 0 ----
    proj_kernel<64, true  ><<<NN / 64, 256>>>(feat, gl_w0,  gl_b0,  pg);
    sq_kernel             <<<NN / 8,  256>>>(pg, psq);
    proj_kernel<128, false><<<NN / 64, 256>>>(feat, gnn_w0, gnn_b0, ph);
    fused_kernel<<<NN / BM, 256, fsm>>>(pg, ph, psq, px1, temp, theta, 1);

    // ---- layer 1 ----
    proj_kernel<64, true  ><<<NN / 64, 256>>>(px1, gl_w1,  gl_b1,  pg);
    sq_kernel             <<<NN / 8,  256>>>(pg, psq);
    proj_kernel<128, false><<<NN / 64, 256>>>(px1, gnn_w1, gnn_b1, ph);
    fused_kernel<<<NN / BM, 256, fsm>>>(pg, ph, psq, px2, temp, theta, 0);

    // ---- head ----
    out_kernel<<<NN / 8, 256>>>(px2, out_w, out_b, out);
}

// round 2
// speedup vs baseline: 1.0024x; 1.0024x over previous
#include <cuda_runtime.h>

#define NN 16384
#define DD 128
#define KG 64
#define BM 64
#define BN 64
#define SKS 65   // padded smem row stride for 64-wide tiles (2-way max conflicts)

// ---------------- scratch (no allocs allowed -> __device__ globals) ----------------
__device__ float g_g [NN*KG];   // graph-learning projection (relu)      [N,64]
__device__ float g_h [NN*DD];   // gnn projection                         [N,128]
__device__ float g_sq[NN];      // row squared norms of g                 [N]
__device__ float g_x1[NN*DD];   // layer-0 output                         [N,128]
__device__ float g_x2[NN*DD];   // layer-1 output                         [N,128]

// ---------------- small GEMM: out[N,CO] = act(x[N,128] @ W[128,CO] + b) ----------------
template<int CO, bool RELU>
__global__ __launch_bounds__(256)
void proj_kernel(const float* __restrict__ x, const float* __restrict__ W,
                 const float* __restrict__ b, float* __restrict__ out)
{
    __shared__ float sX[64 * DD];
    const int tid  = threadIdx.x;
    const long row0 = (long)blockIdx.x * 64;

    #pragma unroll 4
    for (int i = tid; i < 64 * DD; i += 256)
        sX[i] = x[row0 * DD + i];
    __syncthreads();

    constexpr int RPT = CO / 4;       // rows per thread (CO=128 -> 32, CO=64 -> 16)
    const int c  = tid % CO;
    const int rg = tid / CO;

    float acc[RPT];
    #pragma unroll
    for (int i = 0; i < RPT; i++) acc[i] = 0.f;

    #pragma unroll 4
    for (int k = 0; k < DD; k++) {
        const float wv = W[k * CO + c];
        #pragma unroll
        for (int rr = 0; rr < RPT; rr++)
            acc[rr] = fmaf(sX[(rg * RPT + rr) * DD + k], wv, acc[rr]);
    }

    const float bv = b[c];
    #pragma unroll
    for (int rr = 0; rr < RPT; rr++) {
        float v = acc[rr] + bv;
        if (RELU) v = fmaxf(v, 0.f);
        out[(row0 + rg * RPT + rr) * CO + c] = v;
    }
}

// ---------------- row squared norms of g: sq[i] = sum_k g[i,k]^2 ----------------
__global__ __launch_bounds__(256)
void sq_kernel(const float* __restrict__ g, float* __restrict__ sq)
{
    const int warp = (blockIdx.x * blockDim.x + threadIdx.x) >> 5;
    const int lane = threadIdx.x & 31;
    if (warp >= NN) return;
    float a = g[warp * KG + lane];
    float c = g[warp * KG + 32 + lane];
    float s = a * a + c * c;
    #pragma unroll
    for (int off = 16; off; off >>= 1) s += __shfl_xor_sync(~0u, s, off);
    if (lane == 0) sq[warp] = s;
}

// ---------------- fused layer: out = (adj @ h) / rowsum(adj), adj = sigmoid(th - t*dist) --------
// dist[i,j] = sq[i] + sq[j] - 2 * g_i . g_j     (flash-attention-style, adj never materialized)
__global__ __launch_bounds__(256)
void fused_kernel(const float* __restrict__ g, const float* __restrict__ h,
                  const float* __restrict__ sq, float* __restrict__ out,
                  const float* __restrict__ tempp, const float* __restrict__ thetap,
                  int do_relu)
{
    extern __shared__ float sm[];
    float* sV  = sm;                    // [BN, 128]  (16B aligned for float4)
    float* sQ  = sV + BN * DD;          // [BM, SKS]
    float* sK  = sQ + BM * SKS;         // [BN, SKS]  (reused for W after GEMM1)
    float* sqI = sK + BN * SKS;         // [BM]
    float* sqJ = sqI + BM;              // [BN]

    const int tid  = threadIdx.x;
    const int row0 = blockIdx.x * BM;
    const float t  = 1.0f + *tempp;
    const float th = 5.0f + *thetap;
    const float t2 = 2.0f * t;
    const int ty = tid >> 4;            // 0..15 -> Q-row group (4 rows)
    const int tx = tid & 15;            // 0..15 -> col group

    // load persistent Q tile + sqI
    for (int i = tid; i < BM * KG; i += 256) {
        int r = i >> 6, c = i & 63;
        sQ[r * SKS + c] = g[(long)(row0 + r) * KG + c];
    }
    if (tid < BM) sqI[tid] = sq[row0 + tid];

    float acc[4][8];
    float rsum[4];
    #pragma unroll
    for (int i = 0; i < 4; i++) {
        rsum[i] = 0.f;
        #pragma unroll
        for (int c = 0; c < 8; c++) acc[i][c] = 0.f;
    }
    __syncthreads();

    for (int j0 = 0; j0 < NN; j0 += BN) {
        // load K/V tiles
        for (int i = tid; i < BN * KG; i += 256) {
            int r = i >> 6, c = i & 63;
            sK[r * SKS + c] = g[(long)(j0 + r) * KG + c];
        }
        #pragma unroll 4
        for (int i = tid; i < BN * DD; i += 256)
            sV[i] = h[(long)j0 * DD + i];
        if (tid < BN) sqJ[tid] = sq[j0 + tid];
        __syncthreads();

        // GEMM1: S = Q . K^T  (each thread: 4x4)
        float S[4][4];
        #pragma unroll
        for (int i = 0; i < 4; i++)
            #pragma unroll
            for (int jj = 0; jj < 4; jj++) S[i][jj] = 0.f;

        #pragma unroll 4
        for (int k = 0; k < KG; k++) {
            float qv[4], kv[4];
            #pragma unroll
            for (int i = 0; i < 4; i++)  qv[i]  = sQ[(ty * 4 + i) * SKS + k];
            #pragma unroll
            for (int jj = 0; jj < 4; jj++) kv[jj] = sK[(tx * 4 + jj) * SKS + k];
            #pragma unroll
            for (int i = 0; i < 4; i++)
                #pragma unroll
                for (int jj = 0; jj < 4; jj++)
                    S[i][jj] = fmaf(qv[i], kv[jj], S[i][jj]);
        }
        __syncthreads();   // done reading sK -> safe to overwrite with W

        // sigmoid weights -> sK (as W)
        #pragma unroll
        for (int i = 0; i < 4; i++) {
            const float base = th - t * sqI[ty * 4 + i];
            #pragma unroll
            for (int jj = 0; jj < 4; jj++) {
                float z = fmaf(t2, S[i][jj], base - t * sqJ[tx * 4 + jj]);
                float w = 1.0f / (1.0f + __expf(-z));
                sK[(ty * 4 + i) * SKS + (tx * 4 + jj)] = w;
            }
        }
        __syncthreads();

        // GEMM2: acc += W . V ; rsum += W . 1   (each thread: 4 rows x 8 cols)
        #pragma unroll 2
        for (int j = 0; j < BN; j++) {
            const float4 va = *(const float4*)(sV + j * DD + tx * 8);
            const float4 vb = *(const float4*)(sV + j * DD + tx * 8 + 4);
            #pragma unroll
            for (int i = 0; i < 4; i++) {
                const float wv = sK[(ty * 4 + i) * SKS + j];
                rsum[i] += wv;
                acc[i][0] = fmaf(wv, va.x, acc[i][0]);
                acc[i][1] = fmaf(wv, va.y, acc[i][1]);
                acc[i][2] = fmaf(wv, va.z, acc[i][2]);
                acc[i][3] = fmaf(wv, va.w, acc[i][3]);
                acc[i][4] = fmaf(wv, vb.x, acc[i][4]);
                acc[i][5] = fmaf(wv, vb.y, acc[i][5]);
                acc[i][6] = fmaf(wv, vb.z, acc[i][6]);
                acc[i][7] = fmaf(wv, vb.w, acc[i][7]);
            }
        }
        __syncthreads();   // before next tile overwrites sK/sV
    }

    // normalize (+ optional relu) and store
    #pragma unroll
    for (int i = 0; i < 4; i++) {
        const float inv = 1.0f / rsum[i];
        float o[8];
        #pragma unroll
        for (int c = 0; c < 8; c++) {
            float v = acc[i][c] * inv;
            o[c] = do_relu ? fmaxf(v, 0.f) : v;
        }
        float* dst = out + (long)(row0 + ty * 4 + i) * DD + tx * 8;
        *(float4*)(dst)     = make_float4(o[0], o[1], o[2], o[3]);
        *(float4*)(dst + 4) = make_float4(o[4], o[5], o[6], o[7]);
    }
}

// ---------------- output head: softmax(x @ out_w + out_b), one warp per row ----------------
__global__ __launch_bounds__(256)
void out_kernel(const float* __restrict__ x, const float* __restrict__ W,
                const float* __restrict__ b, float* __restrict__ out)
{
    const int row  = (blockIdx.x * blockDim.x + threadIdx.x) >> 5;
    const int lane = threadIdx.x & 31;
    if (row >= NN) return;

    const float* xr = x + (long)row * DD;
    float acc = 0.f;
    if (lane < 10) {
        #pragma unroll 8
        for (int k = 0; k < DD; k++)
            acc = fmaf(xr[k], W[k * 10 + lane], acc);
        acc += b[lane];
    }
    float m = (lane < 10) ? acc : -3.402823466e38f;
    #pragma unroll
    for (int off = 16; off; off >>= 1) m = fmaxf(m, __shfl_xor_sync(~0u, m, off));
    float e = (lane < 10) ? __expf(acc - m) : 0.f;
    float s = e;
    #pragma unroll
    for (int off = 16; off; off >>= 1) s += __shfl_xor_sync(~0u, s, off);
    if (lane < 10) out[(long)row * 10 + lane] = e / s;
}

// ---------------- launch ----------------
extern "C" void kernel_launch(void* const* d_in, const int* in_sizes, int n_in,
                              void* d_out, int out_size)
{
    const float* feat   = (const float*)d_in[0];
    const float* gl_w0  = (const float*)d_in[1];
    const float* gl_b0  = (const float*)d_in[2];
    const float* gl_w1  = (const float*)d_in[3];
    const float* gl_b1  = (const float*)d_in[4];
    const float* gnn_w0 = (const float*)d_in[5];
    const float* gnn_b0 = (const float*)d_in[6];
    const float* gnn_w1 = (const float*)d_in[7];
    const float* gnn_b1 = (const float*)d_in[8];
    const float* out_w  = (const float*)d_in[9];
    const float* out_b  = (const float*)d_in[10];
    const float* temp   = (const float*)d_in[11];
    const float* theta  = (const float*)d_in[12];
    float* out = (float*)d_out;

    float *pg, *ph, *psq, *px1, *px2;
    cudaGetSymbolAddress((void**)&pg,  g_g);
    cudaGetSymbolAddress((void**)&ph,  g_h);
    cudaGetSymbolAddress((void**)&psq, g_sq);
    cudaGetSymbolAddress((void**)&px1, g_x1);
    cudaGetSymbolAddress((void**)&px2, g_x2);

    const int fsm = (BN * DD + BM * SKS + BN * SKS + BM + BN) * (int)sizeof(float);
    cudaFuncSetAttribute(fused_kernel, cudaFuncAttributeMaxDynamicSharedMemorySize, fsm);

    // ---- layer 0 ----
    proj_kernel<64, true  ><<<NN / 64, 256>>>(feat, gl_w0,  gl_b0,  pg);
    sq_kernel             <<<NN / 8,  256>>>(pg, psq);
    proj_kernel<128, false><<<NN / 64, 256>>>(feat, gnn_w0, gnn_b0, ph);
    fused_kernel<<<NN / BM, 256, fsm>>>(pg, ph, psq, px1, temp, theta, 1);

    // ---- layer 1 ----
    proj_kernel<64, true  ><<<NN / 64, 256>>>(px1, gl_w1,  gl_b1,  pg);
    sq_kernel             <<<NN / 8,  256>>>(pg, psq);
    proj_kernel<128, false><<<NN / 64, 256>>>(px1, gnn_w1, gnn_b1, ph);
    fused_kernel<<<NN / BM, 256, fsm>>>(pg, ph, psq, px2, temp, theta, 0);

    // ---- head ----
    out_kernel<<<NN / 8, 256>>>(px2, out_w, out_b, out);
}

// round 4
// speedup vs baseline: 3.9859x; 3.9764x over previous
#include <cuda_runtime.h>
#include <cuda_bf16.h>
#include <cstdint>

#define NN 16384
#define DD 128
#define KG 64
#define BM 128
#define BN 64
#define NTILES (NN / BN)

// ---------------- scratch ----------------
__device__ __align__(16) float          g_g  [NN*KG];
__device__                float         g_sq [NN];
__device__ __align__(16) __nv_bfloat16  g_ghi[NN*KG];
__device__ __align__(16) __nv_bfloat16  g_glo[NN*KG];
__device__ __align__(16) __nv_bfloat16  g_hhi[(size_t)NN*DD];
__device__ __align__(16) __nv_bfloat16  g_hlo[(size_t)NN*DD];
__device__ __align__(16) float          g_x1 [NN*DD];
__device__ __align__(16) float          g_x2 [NN*DD];

// ---------------- helpers ----------------
__device__ __forceinline__ uint32_t smem_u32(const void* p) {
    uint32_t a;
    asm("{ .reg .u64 t; cvta.to.shared.u64 t, %1; cvt.u32.u64 %0, t; }" : "=r"(a) : "l"(p));
    return a;
}
__device__ __forceinline__ void cp16(uint32_t dst, const void* src) {
    asm volatile("cp.async.cg.shared.global [%0], [%1], 16;"
                 :: "r"(dst), "l"(__cvta_generic_to_global(src)) : "memory");
}
#define CP_COMMIT() asm volatile("cp.async.commit_group;" ::: "memory")
#define CP_WAIT1()  asm volatile("cp.async.wait_group 1;" ::: "memory")
#define CP_WAIT0()  asm volatile("cp.async.wait_group 0;" ::: "memory")

__device__ __forceinline__ void ldmx4(uint32_t* r, uint32_t addr) {
    asm volatile("ldmatrix.sync.aligned.m8n8.x4.shared.b16 {%0,%1,%2,%3}, [%4];"
                 : "=r"(r[0]), "=r"(r[1]), "=r"(r[2]), "=r"(r[3]) : "r"(addr));
}
__device__ __forceinline__ void ldmx2(uint32_t* r, uint32_t addr) {
    asm volatile("ldmatrix.sync.aligned.m8n8.x2.shared.b16 {%0,%1}, [%2];"
                 : "=r"(r[0]), "=r"(r[1]) : "r"(addr));
}
__device__ __forceinline__ void ldmx2t(uint32_t* r, uint32_t addr) {
    asm volatile("ldmatrix.sync.aligned.m8n8.x2.trans.shared.b16 {%0,%1}, [%2];"
                 : "=r"(r[0]), "=r"(r[1]) : "r"(addr));
}
__device__ __forceinline__ void mma16816(float* d, const uint32_t* a, const uint32_t* b) {
    asm volatile("mma.sync.aligned.m16n8k16.row.col.f32.bf16.bf16.f32 "
                 "{%0,%1,%2,%3}, {%4,%5,%6,%7}, {%8,%9}, {%0,%1,%2,%3};"
                 : "+f"(d[0]), "+f"(d[1]), "+f"(d[2]), "+f"(d[3])
                 : "r"(a[0]), "r"(a[1]), "r"(a[2]), "r"(a[3]), "r"(b[0]), "r"(b[1]));
}
__device__ __forceinline__ uint32_t pack2(float x, float y) {
    __nv_bfloat162 r = __floats2bfloat162_rn(x, y);
    return *reinterpret_cast<uint32_t*>(&r);
}
__device__ __forceinline__ unsigned short bfbits(__nv_bfloat16 h) { return *reinterpret_cast<unsigned short*>(&h); }

// ---------------- g = relu(x @ gl_w + gl_b) ----------------
__global__ __launch_bounds__(256)
void proj_gl_kernel(const float* __restrict__ x, const float* __restrict__ W,
                    const float* __restrict__ b, float* __restrict__ out)
{
    __shared__ float sX[64 * DD];
    const int tid = threadIdx.x;
    const long row0 = (long)blockIdx.x * 64;
    #pragma unroll 4
    for (int i = tid; i < 64 * DD; i += 256) sX[i] = x[row0 * DD + i];
    __syncthreads();
    const int c = tid % 64, rg = tid / 64;
    float acc[16];
    #pragma unroll
    for (int i = 0; i < 16; i++) acc[i] = 0.f;
    #pragma unroll 4
    for (int k = 0; k < DD; k++) {
        const float wv = W[k * 64 + c];
        #pragma unroll
        for (int rr = 0; rr < 16; rr++)
            acc[rr] = fmaf(sX[(rg * 16 + rr) * DD + k], wv, acc[rr]);
    }
    const float bv = b[c];
    #pragma unroll
    for (int rr = 0; rr < 16; rr++)
        out[(row0 + rg * 16 + rr) * 64 + c] = fmaxf(acc[rr] + bv, 0.f);
}

// ---------------- sq + bf16 hi/lo split of g ----------------
__global__ __launch_bounds__(256)
void sqcvt_kernel(const float* __restrict__ g, float* __restrict__ sq,
                  __nv_bfloat16* __restrict__ ghi, __nv_bfloat16* __restrict__ glo)
{
    const int warp = (blockIdx.x * blockDim.x + threadIdx.x) >> 5;
    const int lane = threadIdx.x & 31;
    float a = g[(size_t)warp * KG + lane];
    float c = g[(size_t)warp * KG + 32 + lane];
    float s = a * a + c * c;
    #pragma unroll
    for (int off = 16; off; off >>= 1) s += __shfl_xor_sync(~0u, s, off);
    if (lane == 0) sq[warp] = s;
    __nv_bfloat16 ha = __float2bfloat16(a), hc = __float2bfloat16(c);
    ghi[(size_t)warp * KG + lane]      = ha;
    ghi[(size_t)warp * KG + 32 + lane] = hc;
    glo[(size_t)warp * KG + lane]      = __float2bfloat16(a - __bfloat162float(ha));
    glo[(size_t)warp * KG + 32 + lane] = __float2bfloat16(c - __bfloat162float(hc));
}

// ---------------- h = x @ gnn_w + b, row-major bf16 hi/lo ----------------
__global__ __launch_bounds__(256)
void proj_gnn_kernel(const float* __restrict__ x, const float* __restrict__ W,
                     const float* __restrict__ b,
                     __nv_bfloat16* __restrict__ hhi, __nv_bfloat16* __restrict__ hlo)
{
    __shared__ float sX[64 * DD];
    const int tid = threadIdx.x;
    const long row0 = (long)blockIdx.x * 64;
    #pragma unroll 4
    for (int i = tid; i < 64 * DD; i += 256) sX[i] = x[row0 * DD + i];
    __syncthreads();
    const int c = tid % 128, rg = tid / 128;
    float acc[32];
    #pragma unroll
    for (int i = 0; i < 32; i++) acc[i] = 0.f;
    #pragma unroll 4
    for (int k = 0; k < DD; k++) {
        const float wv = W[k * 128 + c];
        #pragma unroll
        for (int rr = 0; rr < 32; rr++)
            acc[rr] = fmaf(sX[(rg * 32 + rr) * DD + k], wv, acc[rr]);
    }
    const float bv = b[c];
    #pragma unroll
    for (int rr = 0; rr < 32; rr++) {
        float v = acc[rr] + bv;
        __nv_bfloat16 h = __float2bfloat16(v);
        size_t idx = (size_t)(row0 + rg * 32 + rr) * DD + c;
        hhi[idx] = h;
        hlo[idx] = __float2bfloat16(v - __bfloat162float(h));
    }
}

// ---------------- fused flash layer on HMMA (mma.sync bf16) ----------------
// smem layout (byte offsets): padded rows -> conflict-free ldmatrix, no swizzle
#define QH_OFF 0u
#define QL_OFF 18432u
#define KH_OFF 36864u        // + buf*9216
#define KL_OFF 55296u        // + buf*9216
#define VH_OFF 73728u        // + buf*17408
#define VL_OFF 108544u       // + buf*17408
#define SQ_OFF 143360u       // + buf*256
#define SM_TOTAL 143872u
#define KROW 144u
#define VROW 272u

__global__ __launch_bounds__(256, 1)
void flash_kernel(const __nv_bfloat16* __restrict__ ghi, const __nv_bfloat16* __restrict__ glo,
                  const __nv_bfloat16* __restrict__ hhi, const __nv_bfloat16* __restrict__ hlo,
                  const float* __restrict__ sq, float* __restrict__ outp,
                  const float* __restrict__ tempp, const float* __restrict__ thetap, int do_relu)
{
    extern __shared__ char smem[];
    const uint32_t sb = smem_u32(smem);
    const int tid = threadIdx.x, wid = tid >> 5, lane = tid & 31;
    const int row0 = blockIdx.x * BM;
    const int g = lane >> 2, tq = lane & 3;
    const int mb = wid * 16;

    const float t  = 1.0f + *tempp;
    const float th = 5.0f + *thetap;
    const float t2 = 2.0f * t;
    const float bi0 = th - t * sq[row0 + mb + g];
    const float bi1 = th - t * sq[row0 + mb + 8 + g];

    // ---- prologue: Q tiles (group 0) ----
    #pragma unroll
    for (int i = tid; i < 2048; i += 256) {
        int half = i >> 10, c = i & 1023, row = c >> 3, ch = c & 7;
        const __nv_bfloat16* src = (half ? glo : ghi) + (size_t)(row0 + row) * KG + ch * 8;
        cp16(sb + (half ? QL_OFF : QH_OFF) + row * KROW + ch * 16, src);
    }
    CP_COMMIT();

    // ---- tile 0 (group 1) ----
    {
        const int j0 = 0;
        #pragma unroll 1
        for (int i = tid; i < 3088; i += 256) {
            if (i < 1024) {
                int half = i >> 9, c = i & 511, row = c >> 3, ch = c & 7;
                const __nv_bfloat16* src = (half ? glo : ghi) + (size_t)(j0 + row) * KG + ch * 8;
                cp16(sb + (half ? KL_OFF : KH_OFF) + row * KROW + ch * 16, src);
            } else if (i < 3072) {
                int q = i - 1024, half = q >> 10, c = q & 1023, row = c >> 4, ch = c & 15;
                const __nv_bfloat16* src = (half ? hlo : hhi) + (size_t)(j0 + row) * DD + ch * 8;
                cp16(sb + (half ? VL_OFF : VH_OFF) + row * VROW + ch * 16, src);
            } else {
                int c = i - 3072;
                cp16(sb + SQ_OFF + c * 16, sq + j0 + c * 4);
            }
        }
        CP_COMMIT();
    }

    float o[16][4];
    #pragma unroll
    for (int i = 0; i < 16; i++) { o[i][0] = o[i][1] = o[i][2] = o[i][3] = 0.f; }
    float rs0 = 0.f, rs1 = 0.f;

    // per-lane ldmatrix address components
    const uint32_t q_off  = (uint32_t)(mb + (lane & 15)) * KROW + ((lane & 16) ? 16u : 0u);
    const uint32_t k_off  = (uint32_t)(lane & 7) * KROW + ((lane & 8) ? 16u : 0u);
    const uint32_t v_off  = (uint32_t)(lane & 15) * VROW;

    for (int tt = 0; tt < NTILES; tt++) {
        const int buf = tt & 1;
        if (tt + 1 < NTILES) {
            const int j0 = (tt + 1) * BN, nb = buf ^ 1;
            #pragma unroll 1
            for (int i = tid; i < 3088; i += 256) {
                if (i < 1024) {
                    int half = i >> 9, c = i & 511, row = c >> 3, ch = c & 7;
                    const __nv_bfloat16* src = (half ? glo : ghi) + (size_t)(j0 + row) * KG + ch * 8;
                    cp16(sb + (half ? KL_OFF : KH_OFF) + nb * 9216u + row * KROW + ch * 16, src);
                } else if (i < 3072) {
                    int q = i - 1024, half = q >> 10, c = q & 1023, row = c >> 4, ch = c & 15;
                    const __nv_bfloat16* src = (half ? hlo : hhi) + (size_t)(j0 + row) * DD + ch * 8;
                    cp16(sb + (half ? VL_OFF : VH_OFF) + nb * 17408u + row * VROW + ch * 16, src);
                } else {
                    int c = i - 3072;
                    cp16(sb + SQ_OFF + nb * 256u + c * 16, sq + j0 + c * 4);
                }
            }
            CP_COMMIT();
            CP_WAIT1();
        } else {
            CP_WAIT0();
        }
        __syncthreads();

        const uint32_t khb = sb + KH_OFF + buf * 9216u;
        const uint32_t klb = sb + KL_OFF + buf * 9216u;
        const uint32_t vhb = sb + VH_OFF + buf * 17408u;
        const uint32_t vlb = sb + VL_OFF + buf * 17408u;
        const float* sqj = (const float*)(smem + SQ_OFF + buf * 256u);

        // ---- Q fragments (hi/lo, 4 k-steps) ----
        uint32_t ah[4][4], al[4][4];
        #pragma unroll
        for (int ks = 0; ks < 4; ks++) {
            ldmx4(ah[ks], sb + QH_OFF + q_off + ks * 32);
            ldmx4(al[ks], sb + QL_OFF + q_off + ks * 32);
        }

        // ---- GEMM1: S = Qh.Kh + Qh.Kl + Ql.Kh ----
        float S[8][4];
        #pragma unroll
        for (int nt = 0; nt < 8; nt++) {
            float d[4] = {0.f, 0.f, 0.f, 0.f};
            #pragma unroll
            for (int ks = 0; ks < 4; ks++) {
                uint32_t bh[2], bl[2];
                uint32_t base = (uint32_t)nt * 8 * KROW + k_off + ks * 32;
                ldmx2(bh, khb + base);
                ldmx2(bl, klb + base);
                mma16816(d, ah[ks], bh);
                mma16816(d, ah[ks], bl);
                mma16816(d, al[ks], bh);
            }
            S[nt][0] = d[0]; S[nt][1] = d[1]; S[nt][2] = d[2]; S[nt][3] = d[3];
        }

        // ---- sigmoid -> W fragments (bf16 hi/lo in regs) + rowsum ----
        uint32_t whi[4][4], wlo[4][4];
        #pragma unroll
        for (int nt = 0; nt < 8; nt++) {
            float q0 = sqj[nt * 8 + tq * 2], q1 = sqj[nt * 8 + tq * 2 + 1];
            float c0 = bi0 - t * q0, c1 = bi0 - t * q1;
            float c2 = bi1 - t * q0, c3 = bi1 - t * q1;
            float w0 = __fdividef(1.f, 1.f + __expf(-fmaf(t2, S[nt][0], c0)));
            float w1 = __fdividef(1.f, 1.f + __expf(-fmaf(t2, S[nt][1], c1)));
            float w2 = __fdividef(1.f, 1.f + __expf(-fmaf(t2, S[nt][2], c2)));
            float w3 = __fdividef(1.f, 1.f + __expf(-fmaf(t2, S[nt][3], c3)));
            rs0 += w0 + w1;  rs1 += w2 + w3;
            uint32_t h01 = pack2(w0, w1), h23 = pack2(w2, w3);
            __nv_bfloat162 hh01 = *reinterpret_cast<__nv_bfloat162*>(&h01);
            __nv_bfloat162 hh23 = *reinterpret_cast<__nv_bfloat162*>(&h23);
            uint32_t l01 = pack2(w0 - __bfloat162float(hh01.x), w1 - __bfloat162float(hh01.y));
            uint32_t l23 = pack2(w2 - __bfloat162float(hh23.x), w3 - __bfloat162float(hh23.y));
            const int kj = nt >> 1;
            if ((nt & 1) == 0) { whi[kj][0] = h01; whi[kj][1] = h23; wlo[kj][0] = l01; wlo[kj][1] = l23; }
            else               { whi[kj][2] = h01; whi[kj][3] = h23; wlo[kj][2] = l01; wlo[kj][3] = l23; }
        }

        // ---- GEMM2: O += Wh.Vh + Wh.Vl + Wl.Vh ----
        #pragma unroll
        for (int ct = 0; ct < 16; ct++) {
            const uint32_t cb = (uint32_t)ct * 16;   // ct*8 cols * 2 bytes
            #pragma unroll
            for (int ks = 0; ks < 4; ks++) {
                uint32_t bh[2], bl[2];
                uint32_t base = (uint32_t)ks * 16 * VROW + v_off + cb;
                ldmx2t(bh, vhb + base);
                ldmx2t(bl, vlb + base);
                mma16816(o[ct], whi[ks], bh);
                mma16816(o[ct], whi[ks], bl);
                mma16816(o[ct], wlo[ks], bh);
            }
        }
        __syncthreads();
    }

    // ---- epilogue ----
    rs0 += __shfl_xor_sync(~0u, rs0, 1); rs0 += __shfl_xor_sync(~0u, rs0, 2);
    rs1 += __shfl_xor_sync(~0u, rs1, 1); rs1 += __shfl_xor_sync(~0u, rs1, 2);
    const float inv0 = __fdividef(1.f, rs0);
    const float inv1 = __fdividef(1.f, rs1);
    const size_t r0 = (size_t)(row0 + mb + g) * DD + tq * 2;
    const size_t r1 = r0 + 8 * DD;
    #pragma unroll
    for (int ct = 0; ct < 16; ct++) {
        float2 v0 = make_float2(o[ct][0] * inv0, o[ct][1] * inv0);
        float2 v1 = make_float2(o[ct][2] * inv1, o[ct][3] * inv1);
        if (do_relu) {
            v0.x = fmaxf(v0.x, 0.f); v0.y = fmaxf(v0.y, 0.f);
            v1.x = fmaxf(v1.x, 0.f); v1.y = fmaxf(v1.y, 0.f);
        }
        *(float2*)(outp + r0 + ct * 8) = v0;
        *(float2*)(outp + r1 + ct * 8) = v1;
    }
}

// ---------------- head: softmax(x @ out_w + out_b) ----------------
__global__ __launch_bounds__(256)
void out_kernel(const float* __restrict__ x, const float* __restrict__ W,
                const float* __restrict__ b, float* __restrict__ out)
{
    const int row  = (blockIdx.x * blockDim.x + threadIdx.x) >> 5;
    const int lane = threadIdx.x & 31;
    if (row >= NN) return;
    const float* xr = x + (size_t)row * DD;
    float acc = 0.f;
    if (lane < 10) {
        #pragma unroll 8
        for (int k = 0; k < DD; k++) acc = fmaf(xr[k], W[k * 10 + lane], acc);
        acc += b[lane];
    }
    float m = (lane < 10) ? acc : -3.402823466e38f;
    #pragma unroll
    for (int off = 16; off; off >>= 1) m = fmaxf(m, __shfl_xor_sync(~0u, m, off));
    float e = (lane < 10) ? __expf(acc - m) : 0.f;
    float s = e;
    #pragma unroll
    for (int off = 16; off; off >>= 1) s += __shfl_xor_sync(~0u, s, off);
    if (lane < 10) out[(size_t)row * 10 + lane] = e / s;
}

extern "C" void kernel_launch(void* const* d_in, const int* in_sizes, int n_in,
                              void* d_out, int out_size)
{
    const float* feat   = (const float*)d_in[0];
    const float* gl_w0  = (const float*)d_in[1];
    const float* gl_b0  = (const float*)d_in[2];
    const float* gl_w1  = (const float*)d_in[3];
    const float* gl_b1  = (const float*)d_in[4];
    const float* gnn_w0 = (const float*)d_in[5];
    const float* gnn_b0 = (const float*)d_in[6];
    const float* gnn_w1 = (const float*)d_in[7];
    const float* gnn_b1 = (const float*)d_in[8];
    const float* out_w  = (const float*)d_in[9];
    const float* out_b  = (const float*)d_in[10];
    const float* temp   = (const float*)d_in[11];
    const float* theta  = (const float*)d_in[12];
    float* out = (float*)d_out;

    float *pg, *psq, *px1, *px2;
    __nv_bfloat16 *pghi, *pglo, *phhi, *phlo;
    cudaGetSymbolAddress((void**)&pg,   g_g);
    cudaGetSymbolAddress((void**)&psq,  g_sq);
    cudaGetSymbolAddress((void**)&pghi, g_ghi);
    cudaGetSymbolAddress((void**)&pglo, g_glo);
    cudaGetSymbolAddress((void**)&phhi, g_hhi);
    cudaGetSymbolAddress((void**)&phlo, g_hlo);
    cudaGetSymbolAddress((void**)&px1,  g_x1);
    cudaGetSymbolAddress((void**)&px2,  g_x2);

    cudaFuncSetAttribute(flash_kernel, cudaFuncAttributeMaxDynamicSharedMemorySize, SM_TOTAL);

    proj_gl_kernel <<<NN / 64, 256>>>(feat, gl_w0, gl_b0, pg);
    sqcvt_kernel   <<<NN / 8,  256>>>(pg, psq, pghi, pglo);
    proj_gnn_kernel<<<NN / 64, 256>>>(feat, gnn_w0, gnn_b0, phhi, phlo);
    flash_kernel   <<<NN / BM, 256, SM_TOTAL>>>(pghi, pglo, phhi, phlo, psq, px1, temp, theta, 1);

    proj_gl_kernel <<<NN / 64, 256>>>(px1, gl_w1, gl_b1, pg);
    sqcvt_kernel   <<<NN / 8,  256>>>(pg, psq, pghi, pglo);
    proj_gnn_kernel<<<NN / 64, 256>>>(px1, gnn_w1, gnn_b1, phhi, phlo);
    flash_kernel   <<<NN / BM, 256, SM_TOTAL>>>(pghi, pglo, phhi, phlo, psq, px2, temp, theta, 0);

    out_kernel<<<NN / 8, 256>>>(px2, out_w, out_b, out);
}

// round 6
// speedup vs baseline: 4.9433x; 1.2402x over previous
#include <cuda_runtime.h>
#include <cuda_fp16.h>
#include <cstdint>

#define NN 16384
#define DD 128
#define KG 64
#define BM 128
#define BN 64
#define NTILES (NN / BN)

// ---------------- scratch ----------------
__device__ __align__(16) float  g_g  [NN*KG];
__device__               float  g_sq [NN];
__device__ __align__(16) __half g_ghi[NN*KG];
__device__ __align__(16) __half g_glo[NN*KG];
__device__ __align__(16) __half g_hhi[(size_t)NN*DD];
__device__ __align__(16) __half g_hlo[(size_t)NN*DD];
__device__ __align__(16) float  g_x1 [NN*DD];
__device__ __align__(16) float  g_x2 [NN*DD];

// ---------------- helpers ----------------
__device__ __forceinline__ uint32_t smem_u32(const void* p) {
    uint32_t a;
    asm("{ .reg .u64 t; cvta.to.shared.u64 t, %1; cvt.u32.u64 %0, t; }" : "=r"(a) : "l"(p));
    return a;
}
__device__ __forceinline__ void cp16(uint32_t dst, const void* src) {
    asm volatile("cp.async.cg.shared.global [%0], [%1], 16;"
                 :: "r"(dst), "l"(__cvta_generic_to_global(src)) : "memory");
}
#define CP_COMMIT() asm volatile("cp.async.commit_group;" ::: "memory")
#define CP_WAIT1()  asm volatile("cp.async.wait_group 1;" ::: "memory")
#define CP_WAIT0()  asm volatile("cp.async.wait_group 0;" ::: "memory")

__device__ __forceinline__ void ldmx4(uint32_t* r, uint32_t addr) {
    asm volatile("ldmatrix.sync.aligned.m8n8.x4.shared.b16 {%0,%1,%2,%3}, [%4];"
                 : "=r"(r[0]), "=r"(r[1]), "=r"(r[2]), "=r"(r[3]) : "r"(addr));
}
__device__ __forceinline__ void ldmx4t(uint32_t* r, uint32_t addr) {
    asm volatile("ldmatrix.sync.aligned.m8n8.x4.trans.shared.b16 {%0,%1,%2,%3}, [%4];"
                 : "=r"(r[0]), "=r"(r[1]), "=r"(r[2]), "=r"(r[3]) : "r"(addr));
}
__device__ __forceinline__ void mma16816(float* d, const uint32_t* a, const uint32_t* b) {
    asm volatile("mma.sync.aligned.m16n8k16.row.col.f32.f16.f16.f32 "
                 "{%0,%1,%2,%3}, {%4,%5,%6,%7}, {%8,%9}, {%0,%1,%2,%3};"
                 : "+f"(d[0]), "+f"(d[1]), "+f"(d[2]), "+f"(d[3])
                 : "r"(a[0]), "r"(a[1]), "r"(a[2]), "r"(a[3]), "r"(b[0]), "r"(b[1]));
}
__device__ __forceinline__ uint32_t packh2(float x, float y) {
    __half2 r = __floats2half2_rn(x, y);
    return *reinterpret_cast<uint32_t*>(&r);
}

// ---------------- g = relu(x @ gl_w + gl_b) ----------------
__global__ __launch_bounds__(256)
void proj_gl_kernel(const float* __restrict__ x, const float* __restrict__ W,
                    const float* __restrict__ b, float* __restrict__ out)
{
    __shared__ float sX[64 * DD];
    const int tid = threadIdx.x;
    const long row0 = (long)blockIdx.x * 64;
    #pragma unroll 4
    for (int i = tid; i < 64 * DD; i += 256) sX[i] = x[row0 * DD + i];
    __syncthreads();
    const int c = tid % 64, rg = tid / 64;
    float acc[16];
    #pragma unroll
    for (int i = 0; i < 16; i++) acc[i] = 0.f;
    #pragma unroll 4
    for (int k = 0; k < DD; k++) {
        const float wv = W[k * 64 + c];
        #pragma unroll
        for (int rr = 0; rr < 16; rr++)
            acc[rr] = fmaf(sX[(rg * 16 + rr) * DD + k], wv, acc[rr]);
    }
    const float bv = b[c];
    #pragma unroll
    for (int rr = 0; rr < 16; rr++)
        out[(row0 + rg * 16 + rr) * 64 + c] = fmaxf(acc[rr] + bv, 0.f);
}

// ---------------- sq + fp16 hi/lo split of g ----------------
__global__ __launch_bounds__(256)
void sqcvt_kernel(const float* __restrict__ g, float* __restrict__ sq,
                  __half* __restrict__ ghi, __half* __restrict__ glo)
{
    const int warp = (blockIdx.x * blockDim.x + threadIdx.x) >> 5;
    const int lane = threadIdx.x & 31;
    float a = g[(size_t)warp * KG + lane];
    float c = g[(size_t)warp * KG + 32 + lane];
    float s = a * a + c * c;
    #pragma unroll
    for (int off = 16; off; off >>= 1) s += __shfl_xor_sync(~0u, s, off);
    if (lane == 0) sq[warp] = s;
    __half ha = __float2half_rn(a), hc = __float2half_rn(c);
    ghi[(size_t)warp * KG + lane]      = ha;
    ghi[(size_t)warp * KG + 32 + lane] = hc;
    glo[(size_t)warp * KG + lane]      = __float2half_rn(a - __half2float(ha));
    glo[(size_t)warp * KG + 32 + lane] = __float2half_rn(c - __half2float(hc));
}

// ---------------- h = x @ gnn_w + b, fp16 hi/lo ----------------
__global__ __launch_bounds__(256)
void proj_gnn_kernel(const float* __restrict__ x, const float* __restrict__ W,
                     const float* __restrict__ b,
                     __half* __restrict__ hhi, __half* __restrict__ hlo)
{
    __shared__ float sX[64 * DD];
    const int tid = threadIdx.x;
    const long row0 = (long)blockIdx.x * 64;
    #pragma unroll 4
    for (int i = tid; i < 64 * DD; i += 256) sX[i] = x[row0 * DD + i];
    __syncthreads();
    const int c = tid % 128, rg = tid / 128;
    float acc[32];
    #pragma unroll
    for (int i = 0; i < 32; i++) acc[i] = 0.f;
    #pragma unroll 4
    for (int k = 0; k < DD; k++) {
        const float wv = W[k * 128 + c];
        #pragma unroll
        for (int rr = 0; rr < 32; rr++)
            acc[rr] = fmaf(sX[(rg * 32 + rr) * DD + k], wv, acc[rr]);
    }
    const float bv = b[c];
    #pragma unroll
    for (int rr = 0; rr < 32; rr++) {
        float v = acc[rr] + bv;
        __half h = __float2half_rn(v);
        size_t idx = (size_t)(row0 + rg * 32 + rr) * DD + c;
        hhi[idx] = h;
        hlo[idx] = __float2half_rn(v - __half2float(h));
    }
}

// ---------------- fused flash layer on HMMA (fp16 2-pass) ----------------
#define QH_OFF 0u
#define KH_OFF 18432u        // + buf*9216
#define KL_OFF 36864u        // + buf*9216
#define VH_OFF 55296u        // + buf*17408
#define VL_OFF 90112u        // + buf*17408
#define SQ_OFF 124928u       // + buf*256
#define SM_TOTAL 125440u
#define KROW 144u
#define VROW 272u

__global__ __launch_bounds__(256, 1)
void flash_kernel(const __half* __restrict__ ghi, const __half* __restrict__ glo,
                  const __half* __restrict__ hhi, const __half* __restrict__ hlo,
                  const float* __restrict__ sq, float* __restrict__ outp,
                  const float* __restrict__ tempp, const float* __restrict__ thetap, int do_relu)
{
    extern __shared__ char smem[];
    const uint32_t sb = smem_u32(smem);
    const int tid = threadIdx.x, wid = tid >> 5, lane = tid & 31;
    const int row0 = blockIdx.x * BM;
    const int g = lane >> 2, tq = lane & 3;
    const int mb = wid * 16;

    const float t  = 1.0f + *tempp;
    const float th = 5.0f + *thetap;
    const float t2 = 2.0f * t;
    const float bi0 = th - t * sq[row0 + mb + g];
    const float bi1 = th - t * sq[row0 + mb + 8 + g];

    // ---- prologue: Q hi tile (group 0) ----
    #pragma unroll
    for (int i = tid; i < 1024; i += 256) {
        int row = i >> 3, ch = i & 7;
        cp16(sb + QH_OFF + row * KROW + ch * 16, ghi + (size_t)(row0 + row) * KG + ch * 8);
    }
    CP_COMMIT();

    // ---- tile 0 (group 1) ----
    {
        const int j0 = 0;
        #pragma unroll 1
        for (int i = tid; i < 3088; i += 256) {
            if (i < 1024) {
                int half = i >> 9, c = i & 511, row = c >> 3, ch = c & 7;
                const __half* src = (half ? glo : ghi) + (size_t)(j0 + row) * KG + ch * 8;
                cp16(sb + (half ? KL_OFF : KH_OFF) + row * KROW + ch * 16, src);
            } else if (i < 3072) {
                int q = i - 1024, half = q >> 10, c = q & 1023, row = c >> 4, ch = c & 15;
                const __half* src = (half ? hlo : hhi) + (size_t)(j0 + row) * DD + ch * 8;
                cp16(sb + (half ? VL_OFF : VH_OFF) + row * VROW + ch * 16, src);
            } else {
                int c = i - 3072;
                cp16(sb + SQ_OFF + c * 16, sq + j0 + c * 4);
            }
        }
        CP_COMMIT();
    }

    float o[16][4];
    #pragma unroll
    for (int i = 0; i < 16; i++) { o[i][0] = o[i][1] = o[i][2] = o[i][3] = 0.f; }
    float rs0 = 0.f, rs1 = 0.f;

    // per-lane ldmatrix address components
    const uint32_t q_off  = (uint32_t)(mb + (lane & 15)) * KROW + ((lane & 16) ? 16u : 0u);
    const uint32_t k_off4 = (uint32_t)(lane & 7) * KROW + (uint32_t)(lane >> 3) * 16u;   // x4: 4 k-blocks
    const uint32_t v_off4 = (uint32_t)(lane & 15) * VROW + ((lane & 16) ? 16u : 0u);     // x4t: 2 ct cols

    for (int tt = 0; tt < NTILES; tt++) {
        const int buf = tt & 1;
        if (tt + 1 < NTILES) {
            const int j0 = (tt + 1) * BN, nb = buf ^ 1;
            #pragma unroll 1
            for (int i = tid; i < 3088; i += 256) {
                if (i < 1024) {
                    int half = i >> 9, c = i & 511, row = c >> 3, ch = c & 7;
                    const __half* src = (half ? glo : ghi) + (size_t)(j0 + row) * KG + ch * 8;
                    cp16(sb + (half ? KL_OFF : KH_OFF) + nb * 9216u + row * KROW + ch * 16, src);
                } else if (i < 3072) {
                    int q = i - 1024, half = q >> 10, c = q & 1023, row = c >> 4, ch = c & 15;
                    const __half* src = (half ? hlo : hhi) + (size_t)(j0 + row) * DD + ch * 8;
                    cp16(sb + (half ? VL_OFF : VH_OFF) + nb * 17408u + row * VROW + ch * 16, src);
                } else {
                    int c = i - 3072;
                    cp16(sb + SQ_OFF + nb * 256u + c * 16, sq + j0 + c * 4);
                }
            }
            CP_COMMIT();
            CP_WAIT1();
        } else {
            CP_WAIT0();
        }
        __syncthreads();

        const uint32_t khb = sb + KH_OFF + buf * 9216u;
        const uint32_t klb = sb + KL_OFF + buf * 9216u;
        const uint32_t vhb = sb + VH_OFF + buf * 17408u;
        const uint32_t vlb = sb + VL_OFF + buf * 17408u;
        const float* sqj = (const float*)(smem + SQ_OFF + buf * 256u);

        // ---- Q hi fragments (4 k-steps) ----
        uint32_t ah[4][4];
        #pragma unroll
        for (int ks = 0; ks < 4; ks++)
            ldmx4(ah[ks], sb + QH_OFF + q_off + ks * 32);

        // ---- GEMM1: S = Qh.Kh + Qh.Kl  (x4 B loads: 2 k-steps per load) ----
        float S[8][4];
        #pragma unroll
        for (int nt = 0; nt < 8; nt++) {
            float d[4] = {0.f, 0.f, 0.f, 0.f};
            #pragma unroll
            for (int kp = 0; kp < 2; kp++) {
                uint32_t bh[4], bl[4];
                uint32_t base = (uint32_t)nt * 8 * KROW + k_off4 + kp * 64;
                ldmx4(bh, khb + base);
                ldmx4(bl, klb + base);
                mma16816(d, ah[2*kp],     bh);
                mma16816(d, ah[2*kp],     bl);
                mma16816(d, ah[2*kp + 1], bh + 2);
                mma16816(d, ah[2*kp + 1], bl + 2);
            }
            S[nt][0] = d[0]; S[nt][1] = d[1]; S[nt][2] = d[2]; S[nt][3] = d[3];
        }

        // ---- sigmoid -> W fragments (fp16 in regs) + rowsum ----
        uint32_t whi[4][4];
        #pragma unroll
        for (int nt = 0; nt < 8; nt++) {
            float q0 = sqj[nt * 8 + tq * 2], q1 = sqj[nt * 8 + tq * 2 + 1];
            float c0 = bi0 - t * q0, c1 = bi0 - t * q1;
            float c2 = bi1 - t * q0, c3 = bi1 - t * q1;
            float w0 = __fdividef(1.f, 1.f + __expf(-fmaf(t2, S[nt][0], c0)));
            float w1 = __fdividef(1.f, 1.f + __expf(-fmaf(t2, S[nt][1], c1)));
            float w2 = __fdividef(1.f, 1.f + __expf(-fmaf(t2, S[nt][2], c2)));
            float w3 = __fdividef(1.f, 1.f + __expf(-fmaf(t2, S[nt][3], c3)));
            rs0 += w0 + w1;  rs1 += w2 + w3;
            const int kj = nt >> 1;
            if ((nt & 1) == 0) { whi[kj][0] = packh2(w0, w1); whi[kj][1] = packh2(w2, w3); }
            else               { whi[kj][2] = packh2(w0, w1); whi[kj][3] = packh2(w2, w3); }
        }

        // ---- GEMM2: O += Wh.Vh + Wh.Vl  (x4t loads: 2 ct per load) ----
        #pragma unroll
        for (int ctp = 0; ctp < 8; ctp++) {
            const uint32_t cb = (uint32_t)ctp * 32;   // 2 ct * 8 cols * 2 bytes
            #pragma unroll
            for (int ks = 0; ks < 4; ks++) {
                uint32_t bh[4], bl[4];
                uint32_t base = (uint32_t)ks * 16 * VROW + v_off4 + cb;
                ldmx4t(bh, vhb + base);
                ldmx4t(bl, vlb + base);
                mma16816(o[2*ctp],     whi[ks], bh);
                mma16816(o[2*ctp],     whi[ks], bl);
                mma16816(o[2*ctp + 1], whi[ks], bh + 2);
                mma16816(o[2*ctp + 1], whi[ks], bl + 2);
            }
        }
        __syncthreads();
    }

    // ---- epilogue ----
    rs0 += __shfl_xor_sync(~0u, rs0, 1); rs0 += __shfl_xor_sync(~0u, rs0, 2);
    rs1 += __shfl_xor_sync(~0u, rs1, 1); rs1 += __shfl_xor_sync(~0u, rs1, 2);
    const float inv0 = __fdividef(1.f, rs0);
    const float inv1 = __fdividef(1.f, rs1);
    const size_t r0 = (size_t)(row0 + mb + g) * DD + tq * 2;
    const size_t r1 = r0 + 8 * DD;
    #pragma unroll
    for (int ct = 0; ct < 16; ct++) {
        float2 v0 = make_float2(o[ct][0] * inv0, o[ct][1] * inv0);
        float2 v1 = make_float2(o[ct][2] * inv1, o[ct][3] * inv1);
        if (do_relu) {
            v0.x = fmaxf(v0.x, 0.f); v0.y = fmaxf(v0.y, 0.f);
            v1.x = fmaxf(v1.x, 0.f); v1.y = fmaxf(v1.y, 0.f);
        }
        *(float2*)(outp + r0 + ct * 8) = v0;
        *(float2*)(outp + r1 + ct * 8) = v1;
    }
}

// ---------------- head: softmax(x @ out_w + out_b) ----------------
__global__ __launch_bounds__(256)
void out_kernel(const float* __restrict__ x, const float* __restrict__ W,
                const float* __restrict__ b, float* __restrict__ out)
{
    const int row  = (blockIdx.x * blockDim.x + threadIdx.x) >> 5;
    const int lane = threadIdx.x & 31;
    if (row >= NN) return;
    const float* xr = x + (size_t)row * DD;
    float acc = 0.f;
    if (lane < 10) {
        #pragma unroll 8
        for (int k = 0; k < DD; k++) acc = fmaf(xr[k], W[k * 10 + lane], acc);
        acc += b[lane];
    }
    float m = (lane < 10) ? acc : -3.402823466e38f;
    #pragma unroll
    for (int off = 16; off; off >>= 1) m = fmaxf(m, __shfl_xor_sync(~0u, m, off));
    float e = (lane < 10) ? __expf(acc - m) : 0.f;
    float s = e;
    #pragma unroll
    for (int off = 16; off; off >>= 1) s += __shfl_xor_sync(~0u, s, off);
    if (lane < 10) out[(size_t)row * 10 + lane] = e / s;
}

extern "C" void kernel_launch(void* const* d_in, const int* in_sizes, int n_in,
                              void* d_out, int out_size)
{
    const float* feat   = (const float*)d_in[0];
    const float* gl_w0  = (const float*)d_in[1];
    const float* gl_b0  = (const float*)d_in[2];
    const float* gl_w1  = (const float*)d_in[3];
    const float* gl_b1  = (const float*)d_in[4];
    const float* gnn_w0 = (const float*)d_in[5];
    const float* gnn_b0 = (const float*)d_in[6];
    const float* gnn_w1 = (const float*)d_in[7];
    const float* gnn_b1 = (const float*)d_in[8];
    const float* out_w  = (const float*)d_in[9];
    const float* out_b  = (const float*)d_in[10];
    const float* temp   = (const float*)d_in[11];
    const float* theta  = (const float*)d_in[12];
    float* out = (float*)d_out;

    float *pg, *psq, *px1, *px2;
    __half *pghi, *pglo, *phhi, *phlo;
    cudaGetSymbolAddress((void**)&pg,   g_g);
    cudaGetSymbolAddress((void**)&psq,  g_sq);
    cudaGetSymbolAddress((void**)&pghi, g_ghi);
    cudaGetSymbolAddress((void**)&pglo, g_glo);
    cudaGetSymbolAddress((void**)&phhi, g_hhi);
    cudaGetSymbolAddress((void**)&phlo, g_hlo);
    cudaGetSymbolAddress((void**)&px1,  g_x1);
    cudaGetSymbolAddress((void**)&px2,  g_x2);

    cudaFuncSetAttribute(flash_kernel, cudaFuncAttributeMaxDynamicSharedMemorySize, SM_TOTAL);

    proj_gl_kernel <<<NN / 64, 256>>>(feat, gl_w0, gl_b0, pg);
    sqcvt_kernel   <<<NN / 8,  256>>>(pg, psq, pghi, pglo);
    proj_gnn_kernel<<<NN / 64, 256>>>(feat, gnn_w0, gnn_b0, phhi, phlo);
    flash_kernel   <<<NN / BM, 256, SM_TOTAL>>>(pghi, pglo, phhi, phlo, psq, px1, temp, theta, 1);

    proj_gl_kernel <<<NN / 64, 256>>>(px1, gl_w1, gl_b1, pg);
    sqcvt_kernel   <<<NN / 8,  256>>>(pg, psq, pghi, pglo);
    proj_gnn_kernel<<<NN / 64, 256>>>(px1, gnn_w1, gnn_b1, phhi, phlo);
    flash_kernel   <<<NN / BM, 256, SM_TOTAL>>>(pghi, pglo, phhi, phlo, psq, px2, temp, theta, 0);

    out_kernel<<<NN / 8, 256>>>(px2, out_w, out_b, out);
}

// round 12
// speedup vs baseline: 7.1485x; 1.4461x over previous
#include <cuda_runtime.h>
#include <cuda_fp16.h>
#include <cstdint>

#define NN 16384
#define DD 128
#define KG 64
#define BM 128
#define BN 64
#define NTILES (NN / BN)

// ---------------- scratch ----------------
__device__ __align__(16) float  g_g  [NN*KG];
__device__               float  g_sq [NN];
__device__ __align__(16) __half g_ghi[NN*KG];
__device__ __align__(16) __half g_glo[NN*KG];
__device__ __align__(16) __half g_hhi[(size_t)NN*DD];
__device__ __align__(16) float  g_x1 [NN*DD];
__device__ __align__(16) float  g_x2 [NN*DD];

// ---------------- helpers ----------------
__device__ __forceinline__ uint32_t smem_u32(const void* p) {
    uint32_t a;
    asm("{ .reg .u64 t; cvta.to.shared.u64 t, %1; cvt.u32.u64 %0, t; }" : "=r"(a) : "l"(p));
    return a;
}
__device__ __forceinline__ void cp16(uint32_t dst, const void* src) {
    asm volatile("cp.async.cg.shared.global [%0], [%1], 16;"
                 :: "r"(dst), "l"(__cvta_generic_to_global(src)) : "memory");
}
#define CP_COMMIT() asm volatile("cp.async.commit_group;" ::: "memory")
#define CP_WAIT1()  asm volatile("cp.async.wait_group 1;" ::: "memory")
#define CP_WAIT0()  asm volatile("cp.async.wait_group 0;" ::: "memory")

__device__ __forceinline__ void ldmx4(uint32_t* r, uint32_t addr) {
    asm volatile("ldmatrix.sync.aligned.m8n8.x4.shared.b16 {%0,%1,%2,%3}, [%4];"
                 : "=r"(r[0]), "=r"(r[1]), "=r"(r[2]), "=r"(r[3]) : "r"(addr));
}
__device__ __forceinline__ void ldmx4t(uint32_t* r, uint32_t addr) {
    asm volatile("ldmatrix.sync.aligned.m8n8.x4.trans.shared.b16 {%0,%1,%2,%3}, [%4];"
                 : "=r"(r[0]), "=r"(r[1]), "=r"(r[2]), "=r"(r[3]) : "r"(addr));
}
__device__ __forceinline__ void mma16816(float* d, const uint32_t* a, const uint32_t* b) {
    asm volatile("mma.sync.aligned.m16n8k16.row.col.f32.f16.f16.f32 "
                 "{%0,%1,%2,%3}, {%4,%5,%6,%7}, {%8,%9}, {%0,%1,%2,%3};"
                 : "+f"(d[0]), "+f"(d[1]), "+f"(d[2]), "+f"(d[3])
                 : "r"(a[0]), "r"(a[1]), "r"(a[2]), "r"(a[3]), "r"(b[0]), "r"(b[1]));
}
__device__ __forceinline__ uint32_t packh2(float x, float y) {
    __half2 r = __floats2half2_rn(x, y);
    return *reinterpret_cast<uint32_t*>(&r);
}
__device__ __forceinline__ float tanh_ap(float x) {
    float r;
    asm("tanh.approx.f32 %0, %1;" : "=f"(r) : "f"(x));
    return r;
}

// ---------------- g = relu(x @ gl_w + gl_b) ----------------
__global__ __launch_bounds__(256)
void proj_gl_kernel(const float* __restrict__ x, const float* __restrict__ W,
                    const float* __restrict__ b, float* __restrict__ out)
{
    __shared__ float sX[64 * DD];
    const int tid = threadIdx.x;
    const long row0 = (long)blockIdx.x * 64;
    #pragma unroll 4
    for (int i = tid; i < 64 * DD; i += 256) sX[i] = x[row0 * DD + i];
    __syncthreads();
    const int c = tid % 64, rg = tid / 64;
    float acc[16];
    #pragma unroll
    for (int i = 0; i < 16; i++) acc[i] = 0.f;
    #pragma unroll 4
    for (int k = 0; k < DD; k++) {
        const float wv = W[k * 64 + c];
        #pragma unroll
        for (int rr = 0; rr < 16; rr++)
            acc[rr] = fmaf(sX[(rg * 16 + rr) * DD + k], wv, acc[rr]);
    }
    const float bv = b[c];
    #pragma unroll
    for (int rr = 0; rr < 16; rr++)
        out[(row0 + rg * 16 + rr) * 64 + c] = fmaxf(acc[rr] + bv, 0.f);
}

// ---------------- sq + fp16 hi/lo split of g ----------------
__global__ __launch_bounds__(256)
void sqcvt_kernel(const float* __restrict__ g, float* __restrict__ sq,
                  __half* __restrict__ ghi, __half* __restrict__ glo)
{
    const int warp = (blockIdx.x * blockDim.x + threadIdx.x) >> 5;
    const int lane = threadIdx.x & 31;
    float a = g[(size_t)warp * KG + lane];
    float c = g[(size_t)warp * KG + 32 + lane];
    float s = a * a + c * c;
    #pragma unroll
    for (int off = 16; off; off >>= 1) s += __shfl_xor_sync(~0u, s, off);
    if (lane == 0) sq[warp] = s;
    __half ha = __float2half_rn(a), hc = __float2half_rn(c);
    ghi[(size_t)warp * KG + lane]      = ha;
    ghi[(size_t)warp * KG + 32 + lane] = hc;
    glo[(size_t)warp * KG + lane]      = __float2half_rn(a - __half2float(ha));
    glo[(size_t)warp * KG + 32 + lane] = __float2half_rn(c - __half2float(hc));
}

// ---------------- h = x @ gnn_w + b, fp16 ----------------
__global__ __launch_bounds__(256)
void proj_gnn_kernel(const float* __restrict__ x, const float* __restrict__ W,
                     const float* __restrict__ b, __half* __restrict__ hhi)
{
    __shared__ float sX[64 * DD];
    const int tid = threadIdx.x;
    const long row0 = (long)blockIdx.x * 64;
    #pragma unroll 4
    for (int i = tid; i < 64 * DD; i += 256) sX[i] = x[row0 * DD + i];
    __syncthreads();
    const int c = tid % 128, rg = tid / 128;
    float acc[32];
    #pragma unroll
    for (int i = 0; i < 32; i++) acc[i] = 0.f;
    #pragma unroll 4
    for (int k = 0; k < DD; k++) {
        const float wv = W[k * 128 + c];
        #pragma unroll
        for (int rr = 0; rr < 32; rr++)
            acc[rr] = fmaf(sX[(rg * 32 + rr) * DD + k], wv, acc[rr]);
    }
    const float bv = b[c];
    #pragma unroll
    for (int rr = 0; rr < 32; rr++)
        hhi[(size_t)(row0 + rg * 32 + rr) * DD + c] = __float2half_rn(acc[rr] + bv);
}

// ---------------- fused flash layer ----------------
// GEMM1: two-pass (Qh.Kh + Qh.Kl) -- dist cancellation needs the lo term
// GEMM2: single-pass (Wh.Vh)     -- V truncation averages out under rowsum norm
#define QH_OFF 0u
#define KH_OFF 18432u        // + buf*9216
#define KL_OFF 36864u        // + buf*9216
#define VH_OFF 55296u        // + buf*17408
#define SQ_OFF 90112u        // + buf*256
#define SM_TOTAL 90624u
#define KROW 144u
#define VROW 272u

__global__ __launch_bounds__(256, 1)
void flash_kernel(const __half* __restrict__ ghi, const __half* __restrict__ glo,
                  const __half* __restrict__ hhi,
                  const float* __restrict__ sq, float* __restrict__ outp,
                  const float* __restrict__ tempp, const float* __restrict__ thetap, int do_relu)
{
    extern __shared__ char smem[];
    const uint32_t sb = smem_u32(smem);
    const int tid = threadIdx.x, wid = tid >> 5, lane = tid & 31;
    const int row0 = blockIdx.x * BM;
    const int g = lane >> 2, tq = lane & 3;
    const int mb = wid * 16;

    const float t  = 1.0f + *tempp;
    const float th = 5.0f + *thetap;
    const float tH = 0.5f * t;
    // sigmoid(z) = 0.5*tanh(z/2) + 0.5 ; z/2 = t*S + 0.5*(th - t*sq_i) - 0.5*t*sq_j
    const float bi0h = 0.5f * (th - t * sq[row0 + mb + g]);
    const float bi1h = 0.5f * (th - t * sq[row0 + mb + 8 + g]);

    // ---- prologue: Q tile (group 0) ----
    #pragma unroll
    for (int i = tid; i < 1024; i += 256) {
        int row = i >> 3, ch = i & 7;
        cp16(sb + QH_OFF + row * KROW + ch * 16, ghi + (size_t)(row0 + row) * KG + ch * 8);
    }
    CP_COMMIT();

    // ---- tile 0 (group 1): KH 512 + KL 512 + VH 1024 + SQ 16 = 2064 ops ----
    #pragma unroll 1
    for (int i = tid; i < 2064; i += 256) {
        if (i < 512) {
            int row = i >> 3, ch = i & 7;
            cp16(sb + KH_OFF + row * KROW + ch * 16, ghi + (size_t)row * KG + ch * 8);
        } else if (i < 1024) {
            int c = i - 512, row = c >> 3, ch = c & 7;
            cp16(sb + KL_OFF + row * KROW + ch * 16, glo + (size_t)row * KG + ch * 8);
        } else if (i < 2048) {
            int c = i - 1024, row = c >> 4, ch = c & 15;
            cp16(sb + VH_OFF + row * VROW + ch * 16, hhi + (size_t)row * DD + ch * 8);
        } else {
            int c = i - 2048;                       // 0..15 -> full 64 floats of sq_j
            cp16(sb + SQ_OFF + c * 16, sq + c * 4);
        }
    }
    CP_COMMIT();

    float o[16][4];
    #pragma unroll
    for (int i = 0; i < 16; i++) { o[i][0] = o[i][1] = o[i][2] = o[i][3] = 0.f; }
    float rs0 = 0.f, rs1 = 0.f;

    const uint32_t q_off  = (uint32_t)(mb + (lane & 15)) * KROW + ((lane & 16) ? 16u : 0u);
    const uint32_t k_off4 = (uint32_t)(lane & 7) * KROW + (uint32_t)(lane >> 3) * 16u;
    const uint32_t v_off4 = (uint32_t)(lane & 15) * VROW + ((lane & 16) ? 16u : 0u);

    // Q fragments: persistent across the whole j-loop (QH region never overwritten)
    CP_WAIT1();
    __syncthreads();
    uint32_t ah[4][4];
    #pragma unroll
    for (int ks = 0; ks < 4; ks++)
        ldmx4(ah[ks], sb + QH_OFF + q_off + ks * 32);

    for (int tt = 0; tt < NTILES; tt++) {
        const int buf = tt & 1;
        if (tt + 1 < NTILES) {
            const int j0 = (tt + 1) * BN, nb = buf ^ 1;
            #pragma unroll 1
            for (int i = tid; i < 2064; i += 256) {
                if (i < 512) {
                    int row = i >> 3, ch = i & 7;
                    cp16(sb + KH_OFF + nb * 9216u + row * KROW + ch * 16,
                         ghi + (size_t)(j0 + row) * KG + ch * 8);
                } else if (i < 1024) {
                    int c = i - 512, row = c >> 3, ch = c & 7;
                    cp16(sb + KL_OFF + nb * 9216u + row * KROW + ch * 16,
                         glo + (size_t)(j0 + row) * KG + ch * 8);
                } else if (i < 2048) {
                    int c = i - 1024, row = c >> 4, ch = c & 15;
                    cp16(sb + VH_OFF + nb * 17408u + row * VROW + ch * 16,
                         hhi + (size_t)(j0 + row) * DD + ch * 8);
                } else {
                    int c = i - 2048;               // 0..15 -> full 64 floats
                    cp16(sb + SQ_OFF + nb * 256u + c * 16, sq + j0 + c * 4);
                }
            }
            CP_COMMIT();
            CP_WAIT1();
        } else {
            CP_WAIT0();
        }
        __syncthreads();

        const uint32_t khb = sb + KH_OFF + buf * 9216u;
        const uint32_t klb = sb + KL_OFF + buf * 9216u;
        const uint32_t vhb = sb + VH_OFF + buf * 17408u;
        const float* sqj = (const float*)(smem + SQ_OFF + buf * 256u);

        // ---- GEMM1: S = Qh.Kh + Qh.Kl ----
        float S[8][4];
        #pragma unroll
        for (int nt = 0; nt < 8; nt++) {
            float d[4] = {0.f, 0.f, 0.f, 0.f};
            #pragma unroll
            for (int kp = 0; kp < 2; kp++) {
                uint32_t bh[4], bl[4];
                uint32_t base = (uint32_t)nt * 8 * KROW + k_off4 + kp * 64;
                ldmx4(bh, khb + base);
                ldmx4(bl, klb + base);
                mma16816(d, ah[2*kp],     bh);
                mma16816(d, ah[2*kp],     bl);
                mma16816(d, ah[2*kp + 1], bh + 2);
                mma16816(d, ah[2*kp + 1], bl + 2);
            }
            S[nt][0] = d[0]; S[nt][1] = d[1]; S[nt][2] = d[2]; S[nt][3] = d[3];
        }

        // ---- sigmoid via tanh.approx -> W fragments + rowsum ----
        uint32_t whi[4][4];
        #pragma unroll
        for (int nt = 0; nt < 8; nt++) {
            float q0 = sqj[nt * 8 + tq * 2], q1 = sqj[nt * 8 + tq * 2 + 1];
            float c0 = bi0h - tH * q0, c1 = bi0h - tH * q1;
            float c2 = bi1h - tH * q0, c3 = bi1h - tH * q1;
            float w0 = fmaf(0.5f, tanh_ap(fmaf(t, S[nt][0], c0)), 0.5f);
            float w1 = fmaf(0.5f, tanh_ap(fmaf(t, S[nt][1], c1)), 0.5f);
            float w2 = fmaf(0.5f, tanh_ap(fmaf(t, S[nt][2], c2)), 0.5f);
            float w3 = fmaf(0.5f, tanh_ap(fmaf(t, S[nt][3], c3)), 0.5f);
            rs0 += w0 + w1;  rs1 += w2 + w3;
            const int kj = nt >> 1;
            if ((nt & 1) == 0) { whi[kj][0] = packh2(w0, w1); whi[kj][1] = packh2(w2, w3); }
            else               { whi[kj][2] = packh2(w0, w1); whi[kj][3] = packh2(w2, w3); }
        }

        // ---- GEMM2: O += Wh.Vh ----
        #pragma unroll
        for (int ctp = 0; ctp < 8; ctp++) {
            const uint32_t cb = (uint32_t)ctp * 32;
            #pragma unroll
            for (int ks = 0; ks < 4; ks++) {
                uint32_t bh[4];
                ldmx4t(bh, vhb + (uint32_t)ks * 16 * VROW + v_off4 + cb);
                mma16816(o[2*ctp],     whi[ks], bh);
                mma16816(o[2*ctp + 1], whi[ks], bh + 2);
            }
        }
        __syncthreads();
    }

    // ---- epilogue ----
    rs0 += __shfl_xor_sync(~0u, rs0, 1); rs0 += __shfl_xor_sync(~0u, rs0, 2);
    rs1 += __shfl_xor_sync(~0u, rs1, 1); rs1 += __shfl_xor_sync(~0u, rs1, 2);
    const float inv0 = __fdividef(1.f, rs0);
    const float inv1 = __fdividef(1.f, rs1);
    const size_t r0 = (size_t)(row0 + mb + g) * DD + tq * 2;
    const size_t r1 = r0 + 8 * DD;
    #pragma unroll
    for (int ct = 0; ct < 16; ct++) {
        float2 v0 = make_float2(o[ct][0] * inv0, o[ct][1] * inv0);
        float2 v1 = make_float2(o[ct][2] * inv1, o[ct][3] * inv1);
        if (do_relu) {
            v0.x = fmaxf(v0.x, 0.f); v0.y = fmaxf(v0.y, 0.f);
            v1.x = fmaxf(v1.x, 0.f); v1.y = fmaxf(v1.y, 0.f);
        }
        *(float2*)(outp + r0 + ct * 8) = v0;
        *(float2*)(outp + r1 + ct * 8) = v1;
    }
}

// ---------------- head: softmax(x @ out_w + out_b) ----------------
__global__ __launch_bounds__(256)
void out_kernel(const float* __restrict__ x, const float* __restrict__ W,
                const float* __restrict__ b, float* __restrict__ out)
{
    const int row  = (blockIdx.x * blockDim.x + threadIdx.x) >> 5;
    const int lane = threadIdx.x & 31;
    if (row >= NN) return;
    const float* xr = x + (size_t)row * DD;
    float acc = 0.f;
    if (lane < 10) {
        #pragma unroll 8
        for (int k = 0; k < DD; k++) acc = fmaf(xr[k], W[k * 10 + lane], acc);
        acc += b[lane];
    }
    float m = (lane < 10) ? acc : -3.402823466e38f;
    #pragma unroll
    for (int off = 16; off; off >>= 1) m = fmaxf(m, __shfl_xor_sync(~0u, m, off));
    float e = (lane < 10) ? __expf(acc - m) : 0.f;
    float s = e;
    #pragma unroll
    for (int off = 16; off; off >>= 1) s += __shfl_xor_sync(~0u, s, off);
    if (lane < 10) out[(size_t)row * 10 + lane] = e / s;
}

extern "C" void kernel_launch(void* const* d_in, const int* in_sizes, int n_in,
                              void* d_out, int out_size)
{
    const float* feat   = (const float*)d_in[0];
    const float* gl_w0  = (const float*)d_in[1];
    const float* gl_b0  = (const float*)d_in[2];
    const float* gl_w1  = (const float*)d_in[3];
    const float* gl_b1  = (const float*)d_in[4];
    const float* gnn_w0 = (const float*)d_in[5];
    const float* gnn_b0 = (const float*)d_in[6];
    const float* gnn_w1 = (const float*)d_in[7];
    const float* gnn_b1 = (const float*)d_in[8];
    const float* out_w  = (const float*)d_in[9];
    const float* out_b  = (const float*)d_in[10];
    const float* temp   = (const float*)d_in[11];
    const float* theta  = (const float*)d_in[12];
    float* out = (float*)d_out;

    float *pg, *psq, *px1, *px2;
    __half *pghi, *pglo, *phhi;
    cudaGetSymbolAddress((void**)&pg,   g_g);
    cudaGetSymbolAddress((void**)&psq,  g_sq);
    cudaGetSymbolAddress((void**)&pghi, g_ghi);
    cudaGetSymbolAddress((void**)&pglo, g_glo);
    cudaGetSymbolAddress((void**)&phhi, g_hhi);
    cudaGetSymbolAddress((void**)&px1,  g_x1);
    cudaGetSymbolAddress((void**)&px2,  g_x2);

    cudaFuncSetAttribute(flash_kernel, cudaFuncAttributeMaxDynamicSharedMemorySize, SM_TOTAL);

    proj_gl_kernel <<<NN / 64, 256>>>(feat, gl_w0, gl_b0, pg);
    sqcvt_kernel   <<<NN / 8,  256>>>(pg, psq, pghi, pglo);
    proj_gnn_kernel<<<NN / 64, 256>>>(feat, gnn_w0, gnn_b0, phhi);
    flash_kernel   <<<NN / BM, 256, SM_TOTAL>>>(pghi, pglo, phhi, psq, px1, temp, theta, 1);

    proj_gl_kernel <<<NN / 64, 256>>>(px1, gl_w1, gl_b1, pg);
    sqcvt_kernel   <<<NN / 8,  256>>>(pg, psq, pghi, pglo);
    proj_gnn_kernel<<<NN / 64, 256>>>(px1, gnn_w1, gnn_b1, phhi);
    flash_kernel   <<<NN / BM, 256, SM_TOTAL>>>(pghi, pglo, phhi, psq, px2, temp, theta, 0);

    out_kernel<<<NN / 8, 256>>>(px2, out_w, out_b, out);
}

// round 13
// speedup vs baseline: 9.1980x; 1.2867x over previous
#include <cuda_runtime.h>
#include <cuda_fp16.h>
#include <cstdint>

#define NN 16384
#define DD 128
#define KG 64
#define BM 128
#define BN 64
#define NTILES (NN / BN)

// ---------------- scratch ----------------
__device__ __align__(16) float  g_g  [NN*KG];
__device__               float  g_sq [NN];
__device__ __align__(16) __half g_ghi[NN*KG];
__device__ __align__(16) __half g_hhi[(size_t)NN*DD];
__device__ __align__(16) float  g_x1 [NN*DD];
__device__ __align__(16) float  g_x2 [NN*DD];

// ---------------- helpers ----------------
__device__ __forceinline__ uint32_t smem_u32(const void* p) {
    uint32_t a;
    asm("{ .reg .u64 t; cvta.to.shared.u64 t, %1; cvt.u32.u64 %0, t; }" : "=r"(a) : "l"(p));
    return a;
}
__device__ __forceinline__ void cp16(uint32_t dst, const void* src) {
    asm volatile("cp.async.cg.shared.global [%0], [%1], 16;"
                 :: "r"(dst), "l"(__cvta_generic_to_global(src)) : "memory");
}
#define CP_COMMIT() asm volatile("cp.async.commit_group;" ::: "memory")
#define CP_WAIT1()  asm volatile("cp.async.wait_group 1;" ::: "memory")
#define CP_WAIT0()  asm volatile("cp.async.wait_group 0;" ::: "memory")

__device__ __forceinline__ void ldmx4(uint32_t* r, uint32_t addr) {
    asm volatile("ldmatrix.sync.aligned.m8n8.x4.shared.b16 {%0,%1,%2,%3}, [%4];"
                 : "=r"(r[0]), "=r"(r[1]), "=r"(r[2]), "=r"(r[3]) : "r"(addr));
}
__device__ __forceinline__ void ldmx4t(uint32_t* r, uint32_t addr) {
    asm volatile("ldmatrix.sync.aligned.m8n8.x4.trans.shared.b16 {%0,%1,%2,%3}, [%4];"
                 : "=r"(r[0]), "=r"(r[1]), "=r"(r[2]), "=r"(r[3]) : "r"(addr));
}
__device__ __forceinline__ void mma16816(float* d, const uint32_t* a, const uint32_t* b) {
    asm volatile("mma.sync.aligned.m16n8k16.row.col.f32.f16.f16.f32 "
                 "{%0,%1,%2,%3}, {%4,%5,%6,%7}, {%8,%9}, {%0,%1,%2,%3};"
                 : "+f"(d[0]), "+f"(d[1]), "+f"(d[2]), "+f"(d[3])
                 : "r"(a[0]), "r"(a[1]), "r"(a[2]), "r"(a[3]), "r"(b[0]), "r"(b[1]));
}
__device__ __forceinline__ uint32_t packh2(float x, float y) {
    __half2 r = __floats2half2_rn(x, y);
    return *reinterpret_cast<uint32_t*>(&r);
}
__device__ __forceinline__ float tanh_ap(float x) {
    float r;
    asm("tanh.approx.f32 %0, %1;" : "=f"(r) : "f"(x));
    return r;
}

// ---------------- g = relu(x @ gl_w + gl_b) ----------------
__global__ __launch_bounds__(256)
void proj_gl_kernel(const float* __restrict__ x, const float* __restrict__ W,
                    const float* __restrict__ b, float* __restrict__ out)
{
    __shared__ float sX[64 * DD];
    const int tid = threadIdx.x;
    const long row0 = (long)blockIdx.x * 64;
    #pragma unroll 4
    for (int i = tid; i < 64 * DD; i += 256) sX[i] = x[row0 * DD + i];
    __syncthreads();
    const int c = tid % 64, rg = tid / 64;
    float acc[16];
    #pragma unroll
    for (int i = 0; i < 16; i++) acc[i] = 0.f;
    #pragma unroll 4
    for (int k = 0; k < DD; k++) {
        const float wv = W[k * 64 + c];
        #pragma unroll
        for (int rr = 0; rr < 16; rr++)
            acc[rr] = fmaf(sX[(rg * 16 + rr) * DD + k], wv, acc[rr]);
    }
    const float bv = b[c];
    #pragma unroll
    for (int rr = 0; rr < 16; rr++)
        out[(row0 + rg * 16 + rr) * 64 + c] = fmaxf(acc[rr] + bv, 0.f);
}

// ---------------- sq + fp16 convert of g ----------------
__global__ __launch_bounds__(256)
void sqcvt_kernel(const float* __restrict__ g, float* __restrict__ sq,
                  __half* __restrict__ ghi)
{
    const int warp = (blockIdx.x * blockDim.x + threadIdx.x) >> 5;
    const int lane = threadIdx.x & 31;
    float a = g[(size_t)warp * KG + lane];
    float c = g[(size_t)warp * KG + 32 + lane];
    float s = a * a + c * c;
    #pragma unroll
    for (int off = 16; off; off >>= 1) s += __shfl_xor_sync(~0u, s, off);
    if (lane == 0) sq[warp] = s;
    ghi[(size_t)warp * KG + lane]      = __float2half_rn(a);
    ghi[(size_t)warp * KG + 32 + lane] = __float2half_rn(c);
}

// ---------------- h = x @ gnn_w + b, fp16 ----------------
__global__ __launch_bounds__(256)
void proj_gnn_kernel(const float* __restrict__ x, const float* __restrict__ W,
                     const float* __restrict__ b, __half* __restrict__ hhi)
{
    __shared__ float sX[64 * DD];
    const int tid = threadIdx.x;
    const long row0 = (long)blockIdx.x * 64;
    #pragma unroll 4
    for (int i = tid; i < 64 * DD; i += 256) sX[i] = x[row0 * DD + i];
    __syncthreads();
    const int c = tid % 128, rg = tid / 128;
    float acc[32];
    #pragma unroll
    for (int i = 0; i < 32; i++) acc[i] = 0.f;
    #pragma unroll 4
    for (int k = 0; k < DD; k++) {
        const float wv = W[k * 128 + c];
        #pragma unroll
        for (int rr = 0; rr < 32; rr++)
            acc[rr] = fmaf(sX[(rg * 32 + rr) * DD + k], wv, acc[rr]);
    }
    const float bv = b[c];
    #pragma unroll
    for (int rr = 0; rr < 32; rr++)
        hhi[(size_t)(row0 + rg * 32 + rr) * DD + c] = __float2half_rn(acc[rr] + bv);
}

// ---------------- fused flash layer, single-pass fp16 HMMA ----------------
// Q truncation error already validated at 2.9e-6 output rel_err; K truncation
// is the symmetric term (~doubles dist error, still ~1e-5 at output).
#define QH_OFF 0u
#define KH_OFF 18432u        // + buf*9216
#define VH_OFF 36864u        // + buf*17408
#define SQ_OFF 71680u        // + buf*256
#define SM_TOTAL 72192u
#define KROW 144u
#define VROW 272u

__global__ __launch_bounds__(256, 1)
void flash_kernel(const __half* __restrict__ ghi, const __half* __restrict__ hhi,
                  const float* __restrict__ sq, float* __restrict__ outp,
                  const float* __restrict__ tempp, const float* __restrict__ thetap, int do_relu)
{
    extern __shared__ char smem[];
    const uint32_t sb = smem_u32(smem);
    const int tid = threadIdx.x, wid = tid >> 5, lane = tid & 31;
    const int row0 = blockIdx.x * BM;
    const int g = lane >> 2, tq = lane & 3;
    const int mb = wid * 16;

    const float t  = 1.0f + *tempp;
    const float th = 5.0f + *thetap;
    const float tH = 0.5f * t;
    // sigmoid(z) = 0.5*tanh(z/2) + 0.5 ; z/2 = t*S + 0.5*(th - t*sq_i) - 0.5*t*sq_j
    const float bi0h = 0.5f * (th - t * sq[row0 + mb + g]);
    const float bi1h = 0.5f * (th - t * sq[row0 + mb + 8 + g]);

    // ---- prologue: Q tile (group 0) ----
    #pragma unroll
    for (int i = tid; i < 1024; i += 256) {
        int row = i >> 3, ch = i & 7;
        cp16(sb + QH_OFF + row * KROW + ch * 16, ghi + (size_t)(row0 + row) * KG + ch * 8);
    }
    CP_COMMIT();

    // ---- tile 0 (group 1): KH 512 + VH 1024 + SQ 16 = 1552 ops ----
    #pragma unroll 1
    for (int i = tid; i < 1552; i += 256) {
        if (i < 512) {
            int row = i >> 3, ch = i & 7;
            cp16(sb + KH_OFF + row * KROW + ch * 16, ghi + (size_t)row * KG + ch * 8);
        } else if (i < 1536) {
            int c = i - 512, row = c >> 4, ch = c & 15;
            cp16(sb + VH_OFF + row * VROW + ch * 16, hhi + (size_t)row * DD + ch * 8);
        } else {
            int c = i - 1536;                       // 0..15 -> full 64 floats of sq_j
            cp16(sb + SQ_OFF + c * 16, sq + c * 4);
        }
    }
    CP_COMMIT();

    float o[16][4];
    #pragma unroll
    for (int i = 0; i < 16; i++) { o[i][0] = o[i][1] = o[i][2] = o[i][3] = 0.f; }
    float rs0 = 0.f, rs1 = 0.f;

    const uint32_t q_off  = (uint32_t)(mb + (lane & 15)) * KROW + ((lane & 16) ? 16u : 0u);
    const uint32_t k_off4 = (uint32_t)(lane & 7) * KROW + (uint32_t)(lane >> 3) * 16u;
    const uint32_t v_off4 = (uint32_t)(lane & 15) * VROW + ((lane & 16) ? 16u : 0u);

    // Q fragments: persistent across the whole j-loop (QH region never overwritten)
    CP_WAIT1();
    __syncthreads();
    uint32_t ah[4][4];
    #pragma unroll
    for (int ks = 0; ks < 4; ks++)
        ldmx4(ah[ks], sb + QH_OFF + q_off + ks * 32);

    for (int tt = 0; tt < NTILES; tt++) {
        const int buf = tt & 1;
        if (tt + 1 < NTILES) {
            const int j0 = (tt + 1) * BN, nb = buf ^ 1;
            #pragma unroll 1
            for (int i = tid; i < 1552; i += 256) {
                if (i < 512) {
                    int row = i >> 3, ch = i & 7;
                    cp16(sb + KH_OFF + nb * 9216u + row * KROW + ch * 16,
                         ghi + (size_t)(j0 + row) * KG + ch * 8);
                } else if (i < 1536) {
                    int c = i - 512, row = c >> 4, ch = c & 15;
                    cp16(sb + VH_OFF + nb * 17408u + row * VROW + ch * 16,
                         hhi + (size_t)(j0 + row) * DD + ch * 8);
                } else {
                    int c = i - 1536;               // 0..15 -> full 64 floats
                    cp16(sb + SQ_OFF + nb * 256u + c * 16, sq + j0 + c * 4);
                }
            }
            CP_COMMIT();
            CP_WAIT1();
        } else {
            CP_WAIT0();
        }
        __syncthreads();

        const uint32_t khb = sb + KH_OFF + buf * 9216u;
        const uint32_t vhb = sb + VH_OFF + buf * 17408u;
        const float* sqj = (const float*)(smem + SQ_OFF + buf * 256u);

        // ---- GEMM1: S = Qh.Kh ----
        float S[8][4];
        #pragma unroll
        for (int nt = 0; nt < 8; nt++) {
            float d[4] = {0.f, 0.f, 0.f, 0.f};
            #pragma unroll
            for (int kp = 0; kp < 2; kp++) {
                uint32_t bh[4];
                ldmx4(bh, khb + (uint32_t)nt * 8 * KROW + k_off4 + kp * 64);
                mma16816(d, ah[2*kp],     bh);
                mma16816(d, ah[2*kp + 1], bh + 2);
            }
            S[nt][0] = d[0]; S[nt][1] = d[1]; S[nt][2] = d[2]; S[nt][3] = d[3];
        }

        // ---- sigmoid via tanh.approx -> W fragments + rowsum ----
        uint32_t whi[4][4];
        #pragma unroll
        for (int nt = 0; nt < 8; nt++) {
            float q0 = sqj[nt * 8 + tq * 2], q1 = sqj[nt * 8 + tq * 2 + 1];
            float c0 = bi0h - tH * q0, c1 = bi0h - tH * q1;
            float c2 = bi1h - tH * q0, c3 = bi1h - tH * q1;
            float w0 = fmaf(0.5f, tanh_ap(fmaf(t, S[nt][0], c0)), 0.5f);
            float w1 = fmaf(0.5f, tanh_ap(fmaf(t, S[nt][1], c1)), 0.5f);
            float w2 = fmaf(0.5f, tanh_ap(fmaf(t, S[nt][2], c2)), 0.5f);
            float w3 = fmaf(0.5f, tanh_ap(fmaf(t, S[nt][3], c3)), 0.5f);
            rs0 += w0 + w1;  rs1 += w2 + w3;
            const int kj = nt >> 1;
            if ((nt & 1) == 0) { whi[kj][0] = packh2(w0, w1); whi[kj][1] = packh2(w2, w3); }
            else               { whi[kj][2] = packh2(w0, w1); whi[kj][3] = packh2(w2, w3); }
        }

        // ---- GEMM2: O += Wh.Vh ----
        #pragma unroll
        for (int ctp = 0; ctp < 8; ctp++) {
            const uint32_t cb = (uint32_t)ctp * 32;
            #pragma unroll
            for (int ks = 0; ks < 4; ks++) {
                uint32_t bh[4];
                ldmx4t(bh, vhb + (uint32_t)ks * 16 * VROW + v_off4 + cb);
                mma16816(o[2*ctp],     whi[ks], bh);
                mma16816(o[2*ctp + 1], whi[ks], bh + 2);
            }
        }
        __syncthreads();
    }

    // ---- epilogue ----
    rs0 += __shfl_xor_sync(~0u, rs0, 1); rs0 += __shfl_xor_sync(~0u, rs0, 2);
    rs1 += __shfl_xor_sync(~0u, rs1, 1); rs1 += __shfl_xor_sync(~0u, rs1, 2);
    const float inv0 = __fdividef(1.f, rs0);
    const float inv1 = __fdividef(1.f, rs1);
    const size_t r0 = (size_t)(row0 + mb + g) * DD + tq * 2;
    const size_t r1 = r0 + 8 * DD;
    #pragma unroll
    for (int ct = 0; ct < 16; ct++) {
        float2 v0 = make_float2(o[ct][0] * inv0, o[ct][1] * inv0);
        float2 v1 = make_float2(o[ct][2] * inv1, o[ct][3] * inv1);
        if (do_relu) {
            v0.x = fmaxf(v0.x, 0.f); v0.y = fmaxf(v0.y, 0.f);
            v1.x = fmaxf(v1.x, 0.f); v1.y = fmaxf(v1.y, 0.f);
        }
        *(float2*)(outp + r0 + ct * 8) = v0;
        *(float2*)(outp + r1 + ct * 8) = v1;
    }
}

// ---------------- head: softmax(x @ out_w + out_b) ----------------
__global__ __launch_bounds__(256)
void out_kernel(const float* __restrict__ x, const float* __restrict__ W,
                const float* __restrict__ b, float* __restrict__ out)
{
    const int row  = (blockIdx.x * blockDim.x + threadIdx.x) >> 5;
    const int lane = threadIdx.x & 31;
    if (row >= NN) return;
    const float* xr = x + (size_t)row * DD;
    float acc = 0.f;
    if (lane < 10) {
        #pragma unroll 8
        for (int k = 0; k < DD; k++) acc = fmaf(xr[k], W[k * 10 + lane], acc);
        acc += b[lane];
    }
    float m = (lane < 10) ? acc : -3.402823466e38f;
    #pragma unroll
    for (int off = 16; off; off >>= 1) m = fmaxf(m, __shfl_xor_sync(~0u, m, off));
    float e = (lane < 10) ? __expf(acc - m) : 0.f;
    float s = e;
    #pragma unroll
    for (int off = 16; off; off >>= 1) s += __shfl_xor_sync(~0u, s, off);
    if (lane < 10) out[(size_t)row * 10 + lane] = e / s;
}

extern "C" void kernel_launch(void* const* d_in, const int* in_sizes, int n_in,
                              void* d_out, int out_size)
{
    const float* feat   = (const float*)d_in[0];
    const float* gl_w0  = (const float*)d_in[1];
    const float* gl_b0  = (const float*)d_in[2];
    const float* gl_w1  = (const float*)d_in[3];
    const float* gl_b1  = (const float*)d_in[4];
    const float* gnn_w0 = (const float*)d_in[5];
    const float* gnn_b0 = (const float*)d_in[6];
    const float* gnn_w1 = (const float*)d_in[7];
    const float* gnn_b1 = (const float*)d_in[8];
    const float* out_w  = (const float*)d_in[9];
    const float* out_b  = (const float*)d_in[10];
    const float* temp   = (const float*)d_in[11];
    const float* theta  = (const float*)d_in[12];
    float* out = (float*)d_out;

    float *pg, *psq, *px1, *px2;
    __half *pghi, *phhi;
    cudaGetSymbolAddress((void**)&pg,   g_g);
    cudaGetSymbolAddress((void**)&psq,  g_sq);
    cudaGetSymbolAddress((void**)&pghi, g_ghi);
    cudaGetSymbolAddress((void**)&phhi, g_hhi);
    cudaGetSymbolAddress((void**)&px1,  g_x1);
    cudaGetSymbolAddress((void**)&px2,  g_x2);

    cudaFuncSetAttribute(flash_kernel, cudaFuncAttributeMaxDynamicSharedMemorySize, SM_TOTAL);

    proj_gl_kernel <<<NN / 64, 256>>>(feat, gl_w0, gl_b0, pg);
    sqcvt_kernel   <<<NN / 8,  256>>>(pg, psq, pghi);
    proj_gnn_kernel<<<NN / 64, 256>>>(feat, gnn_w0, gnn_b0, phhi);
    flash_kernel   <<<NN / BM, 256, SM_TOTAL>>>(pghi, phhi, psq, px1, temp, theta, 1);

    proj_gl_kernel <<<NN / 64, 256>>>(px1, gl_w1, gl_b1, pg);
    sqcvt_kernel   <<<NN / 8,  256>>>(pg, psq, pghi);
    proj_gnn_kernel<<<NN / 64, 256>>>(px1, gnn_w1, gnn_b1, phhi);
    flash_kernel   <<<NN / BM, 256, SM_TOTAL>>>(pghi, phhi, psq, px2, temp, theta, 0);

    out_kernel<<<NN / 8, 256>>>(px2, out_w, out_b, out);
}

// round 16
// speedup vs baseline: 9.4842x; 1.0311x over previous
#include <cuda_runtime.h>
#include <cuda_fp16.h>
#include <cstdint>

#define NN 16384
#define DD 128
#define KG 64
#define BM 128
#define JT 128
#define NTILES (NN / JT)

// ---------------- scratch ----------------
__device__ __align__(16) float  g_g  [NN*KG];
__device__               float  g_sq [NN];
__device__ __align__(16) __half g_ghi[NN*KG];
__device__ __align__(16) __half g_hhi[(size_t)NN*DD];
__device__ __align__(16) float  g_x1 [NN*DD];
__device__ __align__(16) float  g_x2 [NN*DD];

// ---------------- helpers ----------------
__device__ __forceinline__ uint32_t smem_u32(const void* p) {
    uint32_t a;
    asm("{ .reg .u64 t; cvta.to.shared.u64 t, %1; cvt.u32.u64 %0, t; }" : "=r"(a) : "l"(p));
    return a;
}
__device__ __forceinline__ void cp16(uint32_t dst, const void* src) {
    asm volatile("cp.async.cg.shared.global [%0], [%1], 16;"
                 :: "r"(dst), "l"(__cvta_generic_to_global(src)) : "memory");
}
#define CP_COMMIT() asm volatile("cp.async.commit_group;" ::: "memory")
#define CP_WAIT1()  asm volatile("cp.async.wait_group 1;" ::: "memory")
#define CP_WAIT0()  asm volatile("cp.async.wait_group 0;" ::: "memory")

__device__ __forceinline__ void ldmx4(uint32_t* r, uint32_t addr) {
    asm volatile("ldmatrix.sync.aligned.m8n8.x4.shared.b16 {%0,%1,%2,%3}, [%4];"
                 : "=r"(r[0]), "=r"(r[1]), "=r"(r[2]), "=r"(r[3]) : "r"(addr));
}
__device__ __forceinline__ void ldmx4t(uint32_t* r, uint32_t addr) {
    asm volatile("ldmatrix.sync.aligned.m8n8.x4.trans.shared.b16 {%0,%1,%2,%3}, [%4];"
                 : "=r"(r[0]), "=r"(r[1]), "=r"(r[2]), "=r"(r[3]) : "r"(addr));
}
__device__ __forceinline__ void mma16816(float* d, const uint32_t* a, const uint32_t* b) {
    asm volatile("mma.sync.aligned.m16n8k16.row.col.f32.f16.f16.f32 "
                 "{%0,%1,%2,%3}, {%4,%5,%6,%7}, {%8,%9}, {%0,%1,%2,%3};"
                 : "+f"(d[0]), "+f"(d[1]), "+f"(d[2]), "+f"(d[3])
                 : "r"(a[0]), "r"(a[1]), "r"(a[2]), "r"(a[3]), "r"(b[0]), "r"(b[1]));
}
__device__ __forceinline__ uint32_t packh2(float x, float y) {
    __half2 r = __floats2half2_rn(x, y);
    return *reinterpret_cast<uint32_t*>(&r);
}
__device__ __forceinline__ float tanh_ap(float x) {
    float r;
    asm("tanh.approx.f32 %0, %1;" : "=f"(r) : "f"(x));
    return r;
}

// ---------------- g = relu(x @ gl_w + gl_b) ----------------
__global__ __launch_bounds__(256)
void proj_gl_kernel(const float* __restrict__ x, const float* __restrict__ W,
                    const float* __restrict__ b, float* __restrict__ out)
{
    __shared__ float sX[64 * DD];
    const int tid = threadIdx.x;
    const long row0 = (long)blockIdx.x * 64;
    #pragma unroll 4
    for (int i = tid; i < 64 * DD; i += 256) sX[i] = x[row0 * DD + i];
    __syncthreads();
    const int c = tid % 64, rg = tid / 64;
    float acc[16];
    #pragma unroll
    for (int i = 0; i < 16; i++) acc[i] = 0.f;
    #pragma unroll 4
    for (int k = 0; k < DD; k++) {
        const float wv = W[k * 64 + c];
        #pragma unroll
        for (int rr = 0; rr < 16; rr++)
            acc[rr] = fmaf(sX[(rg * 16 + rr) * DD + k], wv, acc[rr]);
    }
    const float bv = b[c];
    #pragma unroll
    for (int rr = 0; rr < 16; rr++)
        out[(row0 + rg * 16 + rr) * 64 + c] = fmaxf(acc[rr] + bv, 0.f);
}

// ---------------- sq + fp16 convert of g ----------------
__global__ __launch_bounds__(256)
void sqcvt_kernel(const float* __restrict__ g, float* __restrict__ sq,
                  __half* __restrict__ ghi)
{
    const int warp = (blockIdx.x * blockDim.x + threadIdx.x) >> 5;
    const int lane = threadIdx.x & 31;
    float a = g[(size_t)warp * KG + lane];
    float c = g[(size_t)warp * KG + 32 + lane];
    float s = a * a + c * c;
    #pragma unroll
    for (int off = 16; off; off >>= 1) s += __shfl_xor_sync(~0u, s, off);
    if (lane == 0) sq[warp] = s;
    ghi[(size_t)warp * KG + lane]      = __float2half_rn(a);
    ghi[(size_t)warp * KG + 32 + lane] = __float2half_rn(c);
}

// ---------------- h = x @ gnn_w + b, fp16 ----------------
__global__ __launch_bounds__(256)
void proj_gnn_kernel(const float* __restrict__ x, const float* __restrict__ W,
                     const float* __restrict__ b, __half* __restrict__ hhi)
{
    __shared__ float sX[64 * DD];
    const int tid = threadIdx.x;
    const long row0 = (long)blockIdx.x * 64;
    #pragma unroll 4
    for (int i = tid; i < 64 * DD; i += 256) sX[i] = x[row0 * DD + i];
    __syncthreads();
    const int c = tid % 128, rg = tid / 128;
    float acc[32];
    #pragma unroll
    for (int i = 0; i < 32; i++) acc[i] = 0.f;
    #pragma unroll 4
    for (int k = 0; k < DD; k++) {
        const float wv = W[k * 128 + c];
        #pragma unroll
        for (int rr = 0; rr < 32; rr++)
            acc[rr] = fmaf(sX[(rg * 32 + rr) * DD + k], wv, acc[rr]);
    }
    const float bv = b[c];
    #pragma unroll
    for (int rr = 0; rr < 32; rr++)
        hhi[(size_t)(row0 + rg * 32 + rr) * DD + c] = __float2half_rn(acc[rr] + bv);
}

// ---------------- fused flash layer, single-pass fp16 HMMA, 128-j tiles ----------------
#define QH_OFF 0u
#define KH_OFF 18432u        // + buf*18432
#define VH_OFF 55296u        // + buf*34816
#define SQ_OFF 124928u       // + buf*512
#define SM_TOTAL 125952u
#define KROW 144u
#define VROW 272u

__global__ __launch_bounds__(256, 1)
void flash_kernel(const __half* __restrict__ ghi, const __half* __restrict__ hhi,
                  const float* __restrict__ sq, float* __restrict__ outp,
                  const float* __restrict__ tempp, const float* __restrict__ thetap, int do_relu)
{
    extern __shared__ char smem[];
    const uint32_t sb = smem_u32(smem);
    const int tid = threadIdx.x, wid = tid >> 5, lane = tid & 31;
    const int row0 = blockIdx.x * BM;
    const int g = lane >> 2, tq = lane & 3;
    const int mb = wid * 16;

    const float t  = 1.0f + *tempp;
    const float th = 5.0f + *thetap;
    const float tH = 0.5f * t;
    // sigmoid(z) = 0.5*tanh(z/2) + 0.5 ; z/2 = t*S + 0.5*(th - t*sq_i) - 0.5*t*sq_j
    const float bi0h = 0.5f * (th - t * sq[row0 + mb + g]);
    const float bi1h = 0.5f * (th - t * sq[row0 + mb + 8 + g]);

    // ---- prologue: Q tile (group 0) ----
    #pragma unroll
    for (int i = tid; i < 1024; i += 256) {
        int row = i >> 3, ch = i & 7;
        cp16(sb + QH_OFF + row * KROW + ch * 16, ghi + (size_t)(row0 + row) * KG + ch * 8);
    }
    CP_COMMIT();

    // ---- tile 0 (group 1): K 1024 + V 2048 + SQ 32 = 3104 ops ----
    #pragma unroll 1
    for (int i = tid; i < 3104; i += 256) {
        if (i < 1024) {
            int row = i >> 3, ch = i & 7;
            cp16(sb + KH_OFF + row * KROW + ch * 16, ghi + (size_t)row * KG + ch * 8);
        } else if (i < 3072) {
            int c = i - 1024, row = c >> 4, ch = c & 15;
            cp16(sb + VH_OFF + row * VROW + ch * 16, hhi + (size_t)row * DD + ch * 8);
        } else {
            int c = i - 3072;                       // 0..31 -> 128 floats of sq_j
            cp16(sb + SQ_OFF + c * 16, sq + c * 4);
        }
    }
    CP_COMMIT();

    float o[16][4];
    #pragma unroll
    for (int i = 0; i < 16; i++) { o[i][0] = o[i][1] = o[i][2] = o[i][3] = 0.f; }
    float rs0 = 0.f, rs1 = 0.f;

    const uint32_t q_off  = (uint32_t)(mb + (lane & 15)) * KROW + ((lane & 16) ? 16u : 0u);
    const uint32_t k_off4 = (uint32_t)(lane & 7) * KROW + (uint32_t)(lane >> 3) * 16u;
    const uint32_t v_off4 = (uint32_t)(lane & 15) * VROW + ((lane & 16) ? 16u : 0u);

    // Q fragments: persistent across the whole j-loop
    CP_WAIT1();
    __syncthreads();
    uint32_t ah[4][4];
    #pragma unroll
    for (int ks = 0; ks < 4; ks++)
        ldmx4(ah[ks], sb + QH_OFF + q_off + ks * 32);

    for (int tt = 0; tt < NTILES; tt++) {
        const int buf = tt & 1;
        if (tt + 1 < NTILES) {
            const int j0 = (tt + 1) * JT, nb = buf ^ 1;
            #pragma unroll 1
            for (int i = tid; i < 3104; i += 256) {
                if (i < 1024) {
                    int row = i >> 3, ch = i & 7;
                    cp16(sb + KH_OFF + nb * 18432u + row * KROW + ch * 16,
                         ghi + (size_t)(j0 + row) * KG + ch * 8);
                } else if (i < 3072) {
                    int c = i - 1024, row = c >> 4, ch = c & 15;
                    cp16(sb + VH_OFF + nb * 34816u + row * VROW + ch * 16,
                         hhi + (size_t)(j0 + row) * DD + ch * 8);
                } else {
                    int c = i - 3072;               // 0..31 -> 128 floats
                    cp16(sb + SQ_OFF + nb * 512u + c * 16, sq + j0 + c * 4);
                }
            }
            CP_COMMIT();
            CP_WAIT1();
        } else {
            CP_WAIT0();
        }
        __syncthreads();

        #pragma unroll
        for (int sub = 0; sub < 2; sub++) {
            const uint32_t khb = sb + KH_OFF + buf * 18432u + (uint32_t)sub * 64u * KROW;
            const uint32_t vhb = sb + VH_OFF + buf * 34816u + (uint32_t)sub * 64u * VROW;
            const float* sqj = (const float*)(smem + SQ_OFF + buf * 512u + sub * 256u);

            // ---- GEMM1: S = Qh.Kh (64-j sub-tile) ----
            float S[8][4];
            #pragma unroll
            for (int nt = 0; nt < 8; nt++) {
                float d[4] = {0.f, 0.f, 0.f, 0.f};
                #pragma unroll
                for (int kp = 0; kp < 2; kp++) {
                    uint32_t bh[4];
                    ldmx4(bh, khb + (uint32_t)nt * 8 * KROW + k_off4 + kp * 64);
                    mma16816(d, ah[2*kp],     bh);
                    mma16816(d, ah[2*kp + 1], bh + 2);
                }
                S[nt][0] = d[0]; S[nt][1] = d[1]; S[nt][2] = d[2]; S[nt][3] = d[3];
            }

            // ---- sigmoid via fp32 tanh.approx -> W fragments + rowsum ----
            uint32_t whi[4][4];
            #pragma unroll
            for (int nt = 0; nt < 8; nt++) {
                float q0 = sqj[nt * 8 + tq * 2], q1 = sqj[nt * 8 + tq * 2 + 1];
                float c0 = bi0h - tH * q0, c1 = bi0h - tH * q1;
                float c2 = bi1h - tH * q0, c3 = bi1h - tH * q1;
                float w0 = fmaf(0.5f, tanh_ap(fmaf(t, S[nt][0], c0)), 0.5f);
                float w1 = fmaf(0.5f, tanh_ap(fmaf(t, S[nt][1], c1)), 0.5f);
                float w2 = fmaf(0.5f, tanh_ap(fmaf(t, S[nt][2], c2)), 0.5f);
                float w3 = fmaf(0.5f, tanh_ap(fmaf(t, S[nt][3], c3)), 0.5f);
                rs0 += w0 + w1;  rs1 += w2 + w3;
                const int kj = nt >> 1;
                if ((nt & 1) == 0) { whi[kj][0] = packh2(w0, w1); whi[kj][1] = packh2(w2, w3); }
                else               { whi[kj][2] = packh2(w0, w1); whi[kj][3] = packh2(w2, w3); }
            }

            // ---- GEMM2: O += Wh.Vh ----
            #pragma unroll
            for (int ctp = 0; ctp < 8; ctp++) {
                const uint32_t cb = (uint32_t)ctp * 32;
                #pragma unroll
                for (int ks = 0; ks < 4; ks++) {
                    uint32_t bh[4];
                    ldmx4t(bh, vhb + (uint32_t)ks * 16 * VROW + v_off4 + cb);
                    mma16816(o[2*ctp],     whi[ks], bh);
                    mma16816(o[2*ctp + 1], whi[ks], bh + 2);
                }
            }
        }
        __syncthreads();
    }

    // ---- epilogue ----
    rs0 += __shfl_xor_sync(~0u, rs0, 1); rs0 += __shfl_xor_sync(~0u, rs0, 2);
    rs1 += __shfl_xor_sync(~0u, rs1, 1); rs1 += __shfl_xor_sync(~0u, rs1, 2);
    const float inv0 = __fdividef(1.f, rs0);
    const float inv1 = __fdividef(1.f, rs1);
    const size_t r0 = (size_t)(row0 + mb + g) * DD + tq * 2;
    const size_t r1 = r0 + 8 * DD;
    #pragma unroll
    for (int ct = 0; ct < 16; ct++) {
        float2 v0 = make_float2(o[ct][0] * inv0, o[ct][1] * inv0);
        float2 v1 = make_float2(o[ct][2] * inv1, o[ct][3] * inv1);
        if (do_relu) {
            v0.x = fmaxf(v0.x, 0.f); v0.y = fmaxf(v0.y, 0.f);
            v1.x = fmaxf(v1.x, 0.f); v1.y = fmaxf(v1.y, 0.f);
        }
        *(float2*)(outp + r0 + ct * 8) = v0;
        *(float2*)(outp + r1 + ct * 8) = v1;
    }
}

// ---------------- head: softmax(x @ out_w + out_b) ----------------
__global__ __launch_bounds__(256)
void out_kernel(const float* __restrict__ x, const float* __restrict__ W,
                const float* __restrict__ b, float* __restrict__ out)
{
    const int row  = (blockIdx.x * blockDim.x + threadIdx.x) >> 5;
    const int lane = threadIdx.x & 31;
    if (row >= NN) return;
    const float* xr = x + (size_t)row * DD;
    float acc = 0.f;
    if (lane < 10) {
        #pragma unroll 8
        for (int k = 0; k < DD; k++) acc = fmaf(xr[k], W[k * 10 + lane], acc);
        acc += b[lane];
    }
    float m = (lane < 10) ? acc : -3.402823466e38f;
    #pragma unroll
    for (int off = 16; off; off >>= 1) m = fmaxf(m, __shfl_xor_sync(~0u, m, off));
    float e = (lane < 10) ? __expf(acc - m) : 0.f;
    float s = e;
    #pragma unroll
    for (int off = 16; off; off >>= 1) s += __shfl_xor_sync(~0u, s, off);
    if (lane < 10) out[(size_t)row * 10 + lane] = e / s;
}

extern "C" void kernel_launch(void* const* d_in, const int* in_sizes, int n_in,
                              void* d_out, int out_size)
{
    const float* feat   = (const float*)d_in[0];
    const float* gl_w0  = (const float*)d_in[1];
    const float* gl_b0  = (const float*)d_in[2];
    const float* gl_w1  = (const float*)d_in[3];
    const float* gl_b1  = (const float*)d_in[4];
    const float* gnn_w0 = (const float*)d_in[5];
    const float* gnn_b0 = (const float*)d_in[6];
    const float* gnn_w1 = (const float*)d_in[7];
    const float* gnn_b1 = (const float*)d_in[8];
    const float* out_w  = (const float*)d_in[9];
    const float* out_b  = (const float*)d_in[10];
    const float* temp   = (const float*)d_in[11];
    const float* theta  = (const float*)d_in[12];
    float* out = (float*)d_out;

    float *pg, *psq, *px1, *px2;
    __half *pghi, *phhi;
    cudaGetSymbolAddress((void**)&pg,   g_g);
    cudaGetSymbolAddress((void**)&psq,  g_sq);
    cudaGetSymbolAddress((void**)&pghi, g_ghi);
    cudaGetSymbolAddress((void**)&phhi, g_hhi);
    cudaGetSymbolAddress((void**)&px1,  g_x1);
    cudaGetSymbolAddress((void**)&px2,  g_x2);

    cudaFuncSetAttribute(flash_kernel, cudaFuncAttributeMaxDynamicSharedMemorySize, SM_TOTAL);

    proj_gl_kernel <<<NN / 64, 256>>>(feat, gl_w0, gl_b0, pg);
    sqcvt_kernel   <<<NN / 8,  256>>>(pg, psq, pghi);
    proj_gnn_kernel<<<NN / 64, 256>>>(feat, gnn_w0, gnn_b0, phhi);
    flash_kernel   <<<NN / BM, 256, SM_TOTAL>>>(pghi, phhi, psq, px1, temp, theta, 1);

    proj_gl_kernel <<<NN / 64, 256>>>(px1, gl_w1, gl_b1, pg);
    sqcvt_kernel   <<<NN / 8,  256>>>(pg, psq, pghi);
    proj_gnn_kernel<<<NN / 64, 256>>>(px1, gnn_w1, gnn_b1, phhi);
    flash_kernel   <<<NN / BM, 256, SM_TOTAL>>>(pghi, phhi, psq, px2, temp, theta, 0);

    out_kernel<<<NN / 8, 256>>>(px2, out_w, out_b, out);
}